// round 12
// baseline (speedup 1.0000x reference)
#include <cuda_runtime.h>
#include <cuda_fp16.h>
#include <math.h>
#include <cstdint>

// Problem constants
#define BB 8
#define SS 1024
#define DD 512
#define HH 8
#define DK 64
#define DFF 2048
#define LL 6
#define MM (BB*SS)          // 8192 rows
#define EPS 1e-5f
#define INV_SCALE 0.125f

// fp16 GEMM tiling: 128x128 CTA tile, K-chunk 32 halves, 4-stage pipeline
#define BM 128
#define BN 128
#define BKC 32
#define ROW_U32 20                      // 16 data u32 + 4 pad (conflict-free)
#define TILE_U32 (128*ROW_U32)          // 2560
#define TILE_BYTES_H (TILE_U32*4)       // 10240
#define NSTAGE 4
#define GSMEM_BYTES (NSTAGE*2*TILE_BYTES_H)  // 81920

// fp16 attention smem strides (u32 units)
#define AST 36                          // 72 halves per row (64 data + 8 pad)

// ---------------- scratch ----------------
__device__ float  g_x[MM*DD];           // exact fp32 activations
__device__ __half g_xh[MM*DD];          // half copy (GEMM A operand)
__device__ __half g_qkvh[MM*3*DD];      // QKV in half
__device__ __half g_attnh[MM*DD];       // attention output (half)
__device__ __half g_hh[MM*DFF];         // MLP hidden (half)
__device__ float  g_t2[MM*DD];
// transposed half weights, [N,K] K-major
__device__ __half g_qkv_wt[LL*3*DD*DD];
__device__ __half g_out_wt[LL*DD*DD];
__device__ __half g_w1t[LL*DFF*DD];
__device__ __half g_w2t[LL*DD*DFF];

// ---------------- helpers ----------------
__device__ __forceinline__ uint32_t smem_u32(const void* p) {
    uint32_t a;
    asm("{ .reg .u64 t; cvta.to.shared.u64 t, %1; cvt.u32.u64 %0, t; }" : "=r"(a) : "l"(p));
    return a;
}
__device__ __forceinline__ void cp_async16(uint32_t dst, const void* src) {
    asm volatile("cp.async.cg.shared.global [%0], [%1], 16;" :: "r"(dst), "l"(src));
}
__device__ __forceinline__ void cp_commit() {
    asm volatile("cp.async.commit_group;" ::: "memory");
}
__device__ __forceinline__ void ldsm4(uint32_t& r0, uint32_t& r1, uint32_t& r2,
                                      uint32_t& r3, uint32_t addr) {
    asm volatile("ldmatrix.sync.aligned.m8n8.x4.shared.b16 {%0,%1,%2,%3}, [%4];"
        : "=r"(r0), "=r"(r1), "=r"(r2), "=r"(r3) : "r"(addr));
}
__device__ __forceinline__ void mma16h(float c[4], uint32_t a0, uint32_t a1,
                                       uint32_t a2, uint32_t a3,
                                       uint32_t b0, uint32_t b1) {
    asm volatile(
        "mma.sync.aligned.m16n8k16.row.col.f32.f16.f16.f32 "
        "{%0,%1,%2,%3}, {%4,%5,%6,%7}, {%8,%9}, {%0,%1,%2,%3};"
        : "+f"(c[0]), "+f"(c[1]), "+f"(c[2]), "+f"(c[3])
        : "r"(a0), "r"(a1), "r"(a2), "r"(a3), "r"(b0), "r"(b1));
}
__device__ __forceinline__ uint32_t h2u(__half2 h) { return *(uint32_t*)&h; }

// ---------------- elementwise ----------------
__global__ void copy_half_kernel(const float4* __restrict__ src, float4* __restrict__ dst,
                                 __half2* __restrict__ dsth, int n4) {
    int i = blockIdx.x * blockDim.x + threadIdx.x;
    if (i < n4) {
        float4 v = src[i];
        dst[i] = v;
        dsth[2*i]   = __floats2half2_rn(v.x, v.y);
        dsth[2*i+1] = __floats2half2_rn(v.z, v.w);
    }
}

// transpose + fp16 convert: W[L][K][N] -> Wt[L][N][K]
__global__ void transpose_h(const float* __restrict__ W, __half* __restrict__ Wt,
                            int K, int N) {
    __shared__ float t[32][33];
    const int l = blockIdx.z;
    const float* Wl = W + (size_t)l * K * N;
    __half* Wtl = Wt + (size_t)l * K * N;
    const int k0 = blockIdx.y * 32, n0 = blockIdx.x * 32;
    const int tx = threadIdx.x, ty = threadIdx.y;
#pragma unroll
    for (int i = 0; i < 32; i += 8)
        t[ty + i][tx] = Wl[(size_t)(k0 + ty + i) * N + n0 + tx];
    __syncthreads();
#pragma unroll
    for (int i = 0; i < 32; i += 8)
        Wtl[(size_t)(n0 + ty + i) * K + k0 + tx] = __float2half(t[tx][ty + i]);
}

// ---------------- fp16 mma GEMM: C[M,N] = A[M,K] @ Wt[N,K]^T ----------
// 4-stage cp.async ring, one __syncthreads per chunk, ldmatrix fragments.
template<bool RELU, bool RESID, bool HOUT>
__global__ __launch_bounds__(256)
void tc_gemm(const __half* __restrict__ A, const __half* __restrict__ Bw,
             const float* __restrict__ bias, const float* __restrict__ resid,
             void* __restrict__ Cv, int M, int N, int K)
{
    extern __shared__ float smemf[];
    const uint32_t sb = smem_u32(smemf);

    const int tid = threadIdx.x;
    const int wid = tid >> 5;
    const int lane = tid & 31;
    const int bx = blockIdx.x, by = blockIdx.y;

    const __half* Ag = A + (size_t)by * BM * K;
    const __half* Bg = Bw + (size_t)bx * BN * K;

    auto issue_chunk = [&](int chunk, int buf) {
        const int k0 = chunk * BKC;
        const uint32_t base = sb + (uint32_t)buf * (2u * TILE_BYTES_H);
#pragma unroll
        for (int p = 0; p < 2; p++) {
            const int idx = tid * 2 + p;
            const int row = idx >> 2;
            const int j = idx & 3;
            cp_async16(base + (uint32_t)row * (ROW_U32*4) + (uint32_t)j * 16,
                       Ag + (size_t)row * K + k0 + j * 8);
        }
#pragma unroll
        for (int p = 0; p < 2; p++) {
            const int idx = tid * 2 + p;
            const int row = idx >> 2;
            const int j = idx & 3;
            cp_async16(base + TILE_BYTES_H + (uint32_t)row * (ROW_U32*4) + (uint32_t)j * 16,
                       Bg + (size_t)row * K + k0 + j * 8);
        }
        cp_commit();
    };

    const int nc = K / BKC;        // 16 or 64
    issue_chunk(0, 0);
    issue_chunk(1, 1);
    issue_chunk(2, 2);

    const int wm = (wid >> 2) * 64;
    const int wn = (wid & 3) * 32;
    const int qr = lane >> 2;
    const int qc = lane & 3;

    // ldmatrix per-lane byte offsets
    const uint32_t aoff = (uint32_t)(wm + (lane & 15)) * 80u + (uint32_t)(lane >> 4) * 16u;
    const uint32_t boff = (uint32_t)(wn + ((lane >> 4) << 3) + (lane & 7)) * 80u
                        + (uint32_t)((lane >> 3) & 1) * 16u;

    float acc[4][4][4];
#pragma unroll
    for (int mi = 0; mi < 4; mi++)
#pragma unroll
        for (int ni = 0; ni < 4; ni++)
#pragma unroll
            for (int e = 0; e < 4; e++) acc[mi][ni][e] = 0.f;

    for (int c = 0; c < nc; c++) {
        asm volatile("cp.async.wait_group 2;" ::: "memory");
        __syncthreads();
        if (c + 3 < nc) issue_chunk(c + 3, (c + 3) & 3);

        const uint32_t base = sb + (uint32_t)(c & 3) * (2u * TILE_BYTES_H);
        const uint32_t bA = base + aoff;
        const uint32_t bB = base + TILE_BYTES_H + boff;

#pragma unroll
        for (int ks = 0; ks < 2; ks++) {
            uint32_t b[4][2];
            ldsm4(b[0][0], b[0][1], b[1][0], b[1][1], bB + ks * 32);
            ldsm4(b[2][0], b[2][1], b[3][0], b[3][1], bB + 1280 + ks * 32);
#pragma unroll
            for (int mi = 0; mi < 4; mi++) {
                uint32_t a0, a1, a2, a3;
                ldsm4(a0, a1, a2, a3, bA + mi * 1280 + ks * 32);
#pragma unroll
                for (int ni = 0; ni < 4; ni++)
                    mma16h(acc[mi][ni], a0, a1, a2, a3, b[ni][0], b[ni][1]);
            }
        }
    }

#pragma unroll
    for (int mi = 0; mi < 4; mi++) {
#pragma unroll
        for (int ni = 0; ni < 4; ni++) {
            const int r0 = by * BM + wm + mi * 16 + qr;
            const int c0 = bx * BN + wn + ni * 8 + qc * 2;
            const float2 bv = *(const float2*)(bias + c0);
#pragma unroll
            for (int hrow = 0; hrow < 2; hrow++) {
                const int rr = r0 + hrow * 8;
                float v0 = acc[mi][ni][hrow * 2 + 0] + bv.x;
                float v1 = acc[mi][ni][hrow * 2 + 1] + bv.y;
                if (RESID) {
                    const float2 rv = *(const float2*)(resid + (size_t)rr * N + c0);
                    v0 += rv.x; v1 += rv.y;
                }
                if (RELU) { v0 = fmaxf(v0, 0.f); v1 = fmaxf(v1, 0.f); }
                if (HOUT) {
                    *(__half2*)((__half*)Cv + (size_t)rr * N + c0) = __floats2half2_rn(v0, v1);
                } else {
                    *(float2*)((float*)Cv + (size_t)rr * N + c0) = make_float2(v0, v1);
                }
            }
        }
    }
}

// ---------------- flash attention, full fp16 mma + ldmatrix ----------------
__global__ __launch_bounds__(256, 1)
void attn_h_kernel(const __half* __restrict__ qkvh, __half* __restrict__ outh)
{
    __shared__ uint32_t sQ[128*AST];    // 18432 B
    __shared__ uint32_t sK[64*AST];     //  9216 B
    __shared__ uint32_t sVt[64*AST];    //  9216 B (V transposed: [d][key])

    const int qblk = blockIdx.x;
    const int h = blockIdx.y;
    const int b = blockIdx.z;
    const int tid = threadIdx.x;
    const int w = tid >> 5;
    const int lane = tid & 31;
    const int gr = lane >> 2;
    const int tg = lane & 3;
    const int qbase = qblk * 128;

    // B-style ldmatrix per-lane byte offset (stride AST*4 = 144 B)
    const uint32_t kvoff = (uint32_t)(((lane >> 4) << 3) + (lane & 7)) * (AST*4)
                         + (uint32_t)((lane >> 3) & 1) * 16u;
    const uint32_t sKb = smem_u32(sK) + kvoff;
    const uint32_t sVb = smem_u32(sVt) + kvoff;

    // stage Q tile (half, row-major [128][64])
    {
        const int row = tid >> 1, seg = tid & 1;
        const __half* src = qkvh + ((size_t)(b * SS + qbase + row)) * (3 * DD) + h * DK + seg * 32;
        uint4* dst = (uint4*)(sQ + row * AST + seg * 16);
        const uint4* s4 = (const uint4*)src;
#pragma unroll
        for (int i = 0; i < 4; i++) dst[i] = s4[i];
    }
    __syncthreads();

    // Q A-fragments: 4 k-chunks of 16 halves
    uint32_t qa[4][4];
    {
        const uint32_t* qw = sQ + (w * 16) * AST;
#pragma unroll
        for (int c = 0; c < 4; c++) {
            qa[c][0] = qw[gr * AST + 8 * c + tg];
            qa[c][1] = qw[(gr + 8) * AST + 8 * c + tg];
            qa[c][2] = qw[gr * AST + 8 * c + tg + 4];
            qa[c][3] = qw[(gr + 8) * AST + 8 * c + tg + 4];
        }
    }

    float o[8][4];
#pragma unroll
    for (int nd = 0; nd < 8; nd++)
#pragma unroll
        for (int e = 0; e < 4; e++) o[nd][e] = 0.f;
    float m0 = -1e30f, m1 = -1e30f, l0 = 0.f, l1 = 0.f;

    const int ntiles = 2 * qblk + 2;
    const int wrow_min = qbase + w * 16;

    for (int kt = 0; kt < ntiles; kt++) {
        __syncthreads();
        // load K tile [64 keys][64 dims] and V transposed [64 dims][64 keys]
        {
            const int row = tid >> 2, seg = tid & 3;
            const __half* kb = qkvh + ((size_t)(b * SS + kt * 64 + row)) * (3 * DD)
                             + DD + h * DK + seg * 16;
            uint4* dk = (uint4*)(sK + row * AST + seg * 8);
            dk[0] = ((const uint4*)kb)[0];
            dk[1] = ((const uint4*)kb)[1];

            const __half* vb = kb + DD;
            __half tmp[16];
            *(uint4*)tmp       = ((const uint4*)vb)[0];
            *(uint4*)(tmp + 8) = ((const uint4*)vb)[1];
            __half* vt = (__half*)sVt;
#pragma unroll
            for (int i = 0; i < 16; i++)
                vt[(seg * 16 + i) * (2 * AST) + row] = tmp[i];
        }
        __syncthreads();

        if (kt * 64 > wrow_min + 15) continue;

        // S = Q K^T (fp16), scale 1/8
        float s[8][4];
#pragma unroll
        for (int nb = 0; nb < 8; nb++)
            s[nb][0] = s[nb][1] = s[nb][2] = s[nb][3] = 0.f;
#pragma unroll
        for (int c = 0; c < 4; c++) {
            uint32_t kb2[8][2];
#pragma unroll
            for (int nbp = 0; nbp < 4; nbp++)
                ldsm4(kb2[2*nbp][0], kb2[2*nbp][1], kb2[2*nbp+1][0], kb2[2*nbp+1][1],
                      sKb + (uint32_t)nbp * 2304u + (uint32_t)c * 32u);
#pragma unroll
            for (int nb = 0; nb < 8; nb++)
                mma16h(s[nb], qa[c][0], qa[c][1], qa[c][2], qa[c][3],
                       kb2[nb][0], kb2[nb][1]);
        }
#pragma unroll
        for (int nb = 0; nb < 8; nb++)
#pragma unroll
            for (int e = 0; e < 4; e++) s[nb][e] *= INV_SCALE;

        const int row0 = wrow_min + gr;
        const int row1 = row0 + 8;
        if (kt * 64 + 63 > wrow_min) {
#pragma unroll
            for (int nb = 0; nb < 8; nb++) {
                const int col = kt * 64 + nb * 8 + 2 * tg;
                if (col > row0)     s[nb][0] = -1e30f;
                if (col + 1 > row0) s[nb][1] = -1e30f;
                if (col > row1)     s[nb][2] = -1e30f;
                if (col + 1 > row1) s[nb][3] = -1e30f;
            }
        }

        // online softmax
        float lm0 = -1e30f, lm1 = -1e30f;
#pragma unroll
        for (int nb = 0; nb < 8; nb++) {
            lm0 = fmaxf(lm0, fmaxf(s[nb][0], s[nb][1]));
            lm1 = fmaxf(lm1, fmaxf(s[nb][2], s[nb][3]));
        }
        lm0 = fmaxf(lm0, __shfl_xor_sync(0xffffffffu, lm0, 1));
        lm0 = fmaxf(lm0, __shfl_xor_sync(0xffffffffu, lm0, 2));
        lm1 = fmaxf(lm1, __shfl_xor_sync(0xffffffffu, lm1, 1));
        lm1 = fmaxf(lm1, __shfl_xor_sync(0xffffffffu, lm1, 2));
        const float c0 = __expf(m0 - fmaxf(m0, lm0)), c1 = __expf(m1 - fmaxf(m1, lm1));
        m0 = fmaxf(m0, lm0); m1 = fmaxf(m1, lm1);

        float ps0 = 0.f, ps1 = 0.f;
#pragma unroll
        for (int nb = 0; nb < 8; nb++) {
            s[nb][0] = __expf(s[nb][0] - m0);
            s[nb][1] = __expf(s[nb][1] - m0);
            s[nb][2] = __expf(s[nb][2] - m1);
            s[nb][3] = __expf(s[nb][3] - m1);
            ps0 += s[nb][0] + s[nb][1];
            ps1 += s[nb][2] + s[nb][3];
        }
        ps0 += __shfl_xor_sync(0xffffffffu, ps0, 1);
        ps0 += __shfl_xor_sync(0xffffffffu, ps0, 2);
        ps1 += __shfl_xor_sync(0xffffffffu, ps1, 1);
        ps1 += __shfl_xor_sync(0xffffffffu, ps1, 2);
        l0 = l0 * c0 + ps0;
        l1 = l1 * c1 + ps1;
#pragma unroll
        for (int nd = 0; nd < 8; nd++) {
            o[nd][0] *= c0; o[nd][1] *= c0;
            o[nd][2] *= c1; o[nd][3] *= c1;
        }

        // P -> fp16 register fragments
        uint32_t p01[8], p23[8];
#pragma unroll
        for (int nb = 0; nb < 8; nb++) {
            p01[nb] = h2u(__floats2half2_rn(s[nb][0], s[nb][1]));
            p23[nb] = h2u(__floats2half2_rn(s[nb][2], s[nb][3]));
        }

        // O += P V (B from transposed V tile)
#pragma unroll
        for (int c = 0; c < 4; c++) {
            const uint32_t a0 = p01[2 * c], a1 = p23[2 * c];
            const uint32_t a2 = p01[2 * c + 1], a3 = p23[2 * c + 1];
            uint32_t vb2[8][2];
#pragma unroll
            for (int ndp = 0; ndp < 4; ndp++)
                ldsm4(vb2[2*ndp][0], vb2[2*ndp][1], vb2[2*ndp+1][0], vb2[2*ndp+1][1],
                      sVb + (uint32_t)ndp * 2304u + (uint32_t)c * 32u);
#pragma unroll
            for (int nd = 0; nd < 8; nd++)
                mma16h(o[nd], a0, a1, a2, a3, vb2[nd][0], vb2[nd][1]);
        }
    }

    // epilogue: normalize + half store
    const float il0 = 1.f / l0, il1 = 1.f / l1;
    const int grow0 = b * SS + qbase + w * 16 + gr;
    __half* d0 = outh + (size_t)grow0 * DD + h * DK;
    __half* d1 = d0 + 8 * DD;
#pragma unroll
    for (int nd = 0; nd < 8; nd++) {
        *(__half2*)(d0 + nd * 8 + 2 * tg) = __floats2half2_rn(o[nd][0] * il0, o[nd][1] * il0);
        *(__half2*)(d1 + nd * 8 + 2 * tg) = __floats2half2_rn(o[nd][2] * il1, o[nd][3] * il1);
    }
}

// ---------------- LayerNorm (fp32 out + half out) ----------------
__global__ __launch_bounds__(256)
void ln_kernel(const float* __restrict__ in, const float* __restrict__ gamma,
               const float* __restrict__ beta, float* __restrict__ out,
               __half* __restrict__ outh)
{
    const int row = blockIdx.x;
    const int t = threadIdx.x;
    const float* xr = in + (size_t)row * DD;

    const float2 xv = *(const float2*)(xr + 2 * t);
    float s  = xv.x + xv.y;
    float sq = xv.x * xv.x + xv.y * xv.y;

#pragma unroll
    for (int off = 16; off > 0; off >>= 1) {
        s  += __shfl_xor_sync(0xffffffffu, s,  off);
        sq += __shfl_xor_sync(0xffffffffu, sq, off);
    }
    __shared__ float ss[8], sqq[8];
    if ((t & 31) == 0) { ss[t >> 5] = s; sqq[t >> 5] = sq; }
    __syncthreads();
    float ts = 0.f, tq = 0.f;
#pragma unroll
    for (int wq = 0; wq < 8; wq++) { ts += ss[wq]; tq += sqq[wq]; }

    const float mean = ts * (1.f / DD);
    const float var  = tq * (1.f / DD) - mean * mean;
    const float rstd = rsqrtf(var + EPS);

    const float2 gv = *(const float2*)(gamma + 2 * t);
    const float2 bv = *(const float2*)(beta + 2 * t);
    const float v0 = (xv.x - mean) * rstd * gv.x + bv.x;
    const float v1 = (xv.y - mean) * rstd * gv.y + bv.y;
    *(float2*)(out + (size_t)row * DD + 2 * t) = make_float2(v0, v1);
    *(__half2*)(outh + (size_t)row * DD + 2 * t) = __floats2half2_rn(v0, v1);
}

// ---------------- driver ----------------
extern "C" void kernel_launch(void* const* d_in, const int* in_sizes, int n_in,
                              void* d_out, int out_size)
{
    const float* x      = (const float*)d_in[0];
    const float* qkv_w  = (const float*)d_in[1];
    const float* qkv_b  = (const float*)d_in[2];
    const float* out_w  = (const float*)d_in[3];
    const float* out_b  = (const float*)d_in[4];
    const float* ln1_g  = (const float*)d_in[5];
    const float* ln1_b  = (const float*)d_in[6];
    const float* mlp_w1 = (const float*)d_in[7];
    const float* mlp_b1 = (const float*)d_in[8];
    const float* mlp_w2 = (const float*)d_in[9];
    const float* mlp_b2 = (const float*)d_in[10];
    const float* ln2_g  = (const float*)d_in[11];
    const float* ln2_b  = (const float*)d_in[12];
    float* outp = (float*)d_out;

    float *px, *pt2;
    __half *pxh, *pqkvh, *pattnh, *phh, *pqkvwt, *poutwt, *pw1t, *pw2t;
    cudaGetSymbolAddress((void**)&px,    g_x);
    cudaGetSymbolAddress((void**)&pxh,   g_xh);
    cudaGetSymbolAddress((void**)&pqkvh, g_qkvh);
    cudaGetSymbolAddress((void**)&pattnh,g_attnh);
    cudaGetSymbolAddress((void**)&phh,   g_hh);
    cudaGetSymbolAddress((void**)&pt2,   g_t2);
    cudaGetSymbolAddress((void**)&pqkvwt,g_qkv_wt);
    cudaGetSymbolAddress((void**)&poutwt,g_out_wt);
    cudaGetSymbolAddress((void**)&pw1t,  g_w1t);
    cudaGetSymbolAddress((void**)&pw2t,  g_w2t);

    cudaFuncSetAttribute(tc_gemm<false,false,true>, cudaFuncAttributeMaxDynamicSharedMemorySize, GSMEM_BYTES);
    cudaFuncSetAttribute(tc_gemm<false,true,false>, cudaFuncAttributeMaxDynamicSharedMemorySize, GSMEM_BYTES);
    cudaFuncSetAttribute(tc_gemm<true,false,true>,  cudaFuncAttributeMaxDynamicSharedMemorySize, GSMEM_BYTES);

    transpose_h<<<dim3(3*DD/32, DD/32, LL), dim3(32,8)>>>(qkv_w, pqkvwt, DD, 3*DD);
    transpose_h<<<dim3(DD/32,   DD/32, LL), dim3(32,8)>>>(out_w, poutwt, DD, DD);
    transpose_h<<<dim3(DFF/32,  DD/32, LL), dim3(32,8)>>>(mlp_w1, pw1t, DD, DFF);
    transpose_h<<<dim3(DD/32,  DFF/32, LL), dim3(32,8)>>>(mlp_w2, pw2t, DFF, DD);

    const int nX = MM * DD;
    copy_half_kernel<<<(nX/4 + 255)/256, 256>>>((const float4*)x, (float4*)px,
                                                (__half2*)pxh, nX/4);

    for (int i = 0; i < LL; i++) {
        // QKV: [8192,512] x [512,1536] (+bias) -> half
        tc_gemm<false,false,true><<<dim3(3*DD/BN, MM/BM), 256, GSMEM_BYTES>>>(
            pxh, pqkvwt + (size_t)i * 3*DD*DD, qkv_b + (size_t)i * 3*DD,
            nullptr, pqkvh, MM, 3*DD, DD);

        attn_h_kernel<<<dim3(SS/128, HH, BB), 256>>>(pqkvh, pattnh);

        // out-proj + residual(x) -> fp32 t2
        tc_gemm<false,true,false><<<dim3(DD/BN, MM/BM), 256, GSMEM_BYTES>>>(
            pattnh, poutwt + (size_t)i * DD*DD, out_b + (size_t)i * DD,
            px, pt2, MM, DD, DD);

        ln_kernel<<<MM, 256>>>(pt2, ln1_g + (size_t)i * DD, ln1_b + (size_t)i * DD, px, pxh);

        // MLP1 + ReLU -> half hh
        tc_gemm<true,false,true><<<dim3(DFF/BN, MM/BM), 256, GSMEM_BYTES>>>(
            pxh, pw1t + (size_t)i * DFF*DD, mlp_b1 + (size_t)i * DFF,
            nullptr, phh, MM, DFF, DD);

        // MLP2 + residual(x) -> fp32 t2
        tc_gemm<false,true,false><<<dim3(DD/BN, MM/BM), 256, GSMEM_BYTES>>>(
            phh, pw2t + (size_t)i * DD*DFF, mlp_b2 + (size_t)i * DD,
            px, pt2, MM, DD, DFF);

        float* lnout = (i == LL - 1) ? outp : px;
        ln_kernel<<<MM, 256>>>(pt2, ln2_g + (size_t)i * DD, ln2_b + (size_t)i * DD, lnout, pxh);
    }
}

// round 13
// speedup vs baseline: 1.3961x; 1.3961x over previous
#include <cuda_runtime.h>
#include <cuda_fp16.h>
#include <math.h>
#include <cstdint>

// Problem constants
#define BB 8
#define SS 1024
#define DD 512
#define HH 8
#define DK 64
#define DFF 2048
#define LL 6
#define MM (BB*SS)          // 8192 rows
#define EPS 1e-5f
#define INV_SCALE 0.125f

// fp16 GEMM tiling: 128x128 CTA tile, K-chunk 32 halves, 3-stage pipeline
#define BM 128
#define BN 128
#define BKC 32
#define ROW_U32 20                      // 16 data u32 + 4 pad (conflict-free)
#define TILE_U32 (128*ROW_U32)          // 2560
#define TILE_BYTES_H (TILE_U32*4)       // 10240
#define NSTAGE 3
#define GSMEM_BYTES (NSTAGE*2*TILE_BYTES_H)  // 61440

// fp16 attention smem strides (u32 units)
#define AST 36                          // 72 halves per row (64 data + 8 pad)

// ---------------- scratch ----------------
__device__ float  g_x[MM*DD];           // exact fp32 activations
__device__ __half g_xh[MM*DD];          // half copy (GEMM A operand)
__device__ __half g_qkvh[MM*3*DD];      // QKV in half
__device__ __half g_attnh[MM*DD];       // attention output (half)
__device__ __half g_hh[MM*DFF];         // MLP hidden (half)
__device__ float  g_t2[MM*DD];
// transposed half weights, [N,K] K-major
__device__ __half g_qkv_wt[LL*3*DD*DD];
__device__ __half g_out_wt[LL*DD*DD];
__device__ __half g_w1t[LL*DFF*DD];
__device__ __half g_w2t[LL*DD*DFF];

// ---------------- helpers ----------------
__device__ __forceinline__ uint32_t smem_u32(const void* p) {
    uint32_t a;
    asm("{ .reg .u64 t; cvta.to.shared.u64 t, %1; cvt.u32.u64 %0, t; }" : "=r"(a) : "l"(p));
    return a;
}
__device__ __forceinline__ void cp_async16(uint32_t dst, const void* src) {
    asm volatile("cp.async.cg.shared.global [%0], [%1], 16;" :: "r"(dst), "l"(src));
}
__device__ __forceinline__ void cp_commit() {
    asm volatile("cp.async.commit_group;" ::: "memory");
}
__device__ __forceinline__ void mma16h(float c[4], uint32_t a0, uint32_t a1,
                                       uint32_t a2, uint32_t a3,
                                       uint32_t b0, uint32_t b1) {
    asm volatile(
        "mma.sync.aligned.m16n8k16.row.col.f32.f16.f16.f32 "
        "{%0,%1,%2,%3}, {%4,%5,%6,%7}, {%8,%9}, {%0,%1,%2,%3};"
        : "+f"(c[0]), "+f"(c[1]), "+f"(c[2]), "+f"(c[3])
        : "r"(a0), "r"(a1), "r"(a2), "r"(a3), "r"(b0), "r"(b1));
}
__device__ __forceinline__ uint32_t h2u(__half2 h) { return *(uint32_t*)&h; }

// ---------------- elementwise ----------------
__global__ void copy_half_kernel(const float4* __restrict__ src, float4* __restrict__ dst,
                                 __half2* __restrict__ dsth, int n4) {
    int i = blockIdx.x * blockDim.x + threadIdx.x;
    if (i < n4) {
        float4 v = src[i];
        dst[i] = v;
        dsth[2*i]   = __floats2half2_rn(v.x, v.y);
        dsth[2*i+1] = __floats2half2_rn(v.z, v.w);
    }
}

// transpose + fp16 convert: W[L][K][N] -> Wt[L][N][K]
__global__ void transpose_h(const float* __restrict__ W, __half* __restrict__ Wt,
                            int K, int N) {
    __shared__ float t[32][33];
    const int l = blockIdx.z;
    const float* Wl = W + (size_t)l * K * N;
    __half* Wtl = Wt + (size_t)l * K * N;
    const int k0 = blockIdx.y * 32, n0 = blockIdx.x * 32;
    const int tx = threadIdx.x, ty = threadIdx.y;
#pragma unroll
    for (int i = 0; i < 32; i += 8)
        t[ty + i][tx] = Wl[(size_t)(k0 + ty + i) * N + n0 + tx];
    __syncthreads();
#pragma unroll
    for (int i = 0; i < 32; i += 8)
        Wtl[(size_t)(n0 + ty + i) * K + k0 + tx] = __float2half(t[tx][ty + i]);
}

// ---------------- fp16 mma GEMM: C[M,N] = A[M,K] @ Wt[N,K]^T ----------
// Round-9 structure (scalar LDS fragments, two syncs/chunk), 3-stage ring.
template<bool RELU, bool RESID, bool HOUT>
__global__ __launch_bounds__(256)
void tc_gemm(const __half* __restrict__ A, const __half* __restrict__ Bw,
             const float* __restrict__ bias, const float* __restrict__ resid,
             void* __restrict__ Cv, int M, int N, int K)
{
    extern __shared__ float smemf[];
    const uint32_t sb = smem_u32(smemf);

    const int tid = threadIdx.x;
    const int wid = tid >> 5;
    const int lane = tid & 31;
    const int bx = blockIdx.x, by = blockIdx.y;

    const __half* Ag = A + (size_t)by * BM * K;
    const __half* Bg = Bw + (size_t)bx * BN * K;

    auto issue_chunk = [&](int chunk, int buf) {
        const int k0 = chunk * BKC;
        const uint32_t base = sb + (uint32_t)buf * (2u * TILE_BYTES_H);
#pragma unroll
        for (int p = 0; p < 2; p++) {
            const int idx = tid * 2 + p;
            const int row = idx >> 2;
            const int j = idx & 3;
            cp_async16(base + (uint32_t)row * (ROW_U32*4) + (uint32_t)j * 16,
                       Ag + (size_t)row * K + k0 + j * 8);
        }
#pragma unroll
        for (int p = 0; p < 2; p++) {
            const int idx = tid * 2 + p;
            const int row = idx >> 2;
            const int j = idx & 3;
            cp_async16(base + TILE_BYTES_H + (uint32_t)row * (ROW_U32*4) + (uint32_t)j * 16,
                       Bg + (size_t)row * K + k0 + j * 8);
        }
        cp_commit();
    };

    const int nc = K / BKC;        // 16 or 64 (always >= 3)
    issue_chunk(0, 0);
    issue_chunk(1, 1);
    issue_chunk(2, 2);

    const int wm = (wid >> 2) * 64;
    const int wn = (wid & 3) * 32;
    const int qr = lane >> 2;
    const int qc = lane & 3;

    float acc[4][4][4];
#pragma unroll
    for (int mi = 0; mi < 4; mi++)
#pragma unroll
        for (int ni = 0; ni < 4; ni++)
#pragma unroll
            for (int e = 0; e < 4; e++) acc[mi][ni][e] = 0.f;

    int buf = 0;
    for (int c = 0; c < nc; c++) {
        const int ahead = nc - 1 - c;
        if (ahead >= 2)      asm volatile("cp.async.wait_group 2;" ::: "memory");
        else if (ahead == 1) asm volatile("cp.async.wait_group 1;" ::: "memory");
        else                 asm volatile("cp.async.wait_group 0;" ::: "memory");
        __syncthreads();

        const uint32_t* sAu = reinterpret_cast<const uint32_t*>(smemf) + buf * (2 * TILE_U32);
        const uint32_t* sBu = sAu + TILE_U32;

#pragma unroll
        for (int ks = 0; ks < 2; ks++) {
            const int col = ks * 8 + qc;
            uint32_t bfr[4][2];
#pragma unroll
            for (int ni = 0; ni < 4; ni++) {
                const int n = wn + ni * 8 + qr;
                bfr[ni][0] = sBu[n * ROW_U32 + col];
                bfr[ni][1] = sBu[n * ROW_U32 + col + 4];
            }
#pragma unroll
            for (int mi = 0; mi < 4; mi++) {
                const int r = wm + mi * 16 + qr;
                const uint32_t a0 = sAu[r * ROW_U32 + col];
                const uint32_t a1 = sAu[(r + 8) * ROW_U32 + col];
                const uint32_t a2 = sAu[r * ROW_U32 + col + 4];
                const uint32_t a3 = sAu[(r + 8) * ROW_U32 + col + 4];
#pragma unroll
                for (int ni = 0; ni < 4; ni++)
                    mma16h(acc[mi][ni], a0, a1, a2, a3, bfr[ni][0], bfr[ni][1]);
            }
        }
        __syncthreads();
        if (c + 3 < nc) issue_chunk(c + 3, buf);
        buf = (buf == NSTAGE - 1) ? 0 : buf + 1;
    }

#pragma unroll
    for (int mi = 0; mi < 4; mi++) {
#pragma unroll
        for (int ni = 0; ni < 4; ni++) {
            const int r0 = by * BM + wm + mi * 16 + qr;
            const int c0 = bx * BN + wn + ni * 8 + qc * 2;
            const float2 bv = *(const float2*)(bias + c0);
#pragma unroll
            for (int hrow = 0; hrow < 2; hrow++) {
                const int rr = r0 + hrow * 8;
                float v0 = acc[mi][ni][hrow * 2 + 0] + bv.x;
                float v1 = acc[mi][ni][hrow * 2 + 1] + bv.y;
                if (RESID) {
                    const float2 rv = *(const float2*)(resid + (size_t)rr * N + c0);
                    v0 += rv.x; v1 += rv.y;
                }
                if (RELU) { v0 = fmaxf(v0, 0.f); v1 = fmaxf(v1, 0.f); }
                if (HOUT) {
                    *(__half2*)((__half*)Cv + (size_t)rr * N + c0) = __floats2half2_rn(v0, v1);
                } else {
                    *(float2*)((float*)Cv + (size_t)rr * N + c0) = make_float2(v0, v1);
                }
            }
        }
    }
}

// ---------------- flash attention, full fp16 mma (round-9 proven form) ------
__global__ __launch_bounds__(256, 1)
void attn_h_kernel(const __half* __restrict__ qkvh, __half* __restrict__ outh)
{
    __shared__ uint32_t sQ[128*AST];    // 18432 B
    __shared__ uint32_t sK[64*AST];     //  9216 B
    __shared__ uint32_t sVt[64*AST];    //  9216 B (V transposed: [d][key])

    const int qblk = blockIdx.x;
    const int h = blockIdx.y;
    const int b = blockIdx.z;
    const int tid = threadIdx.x;
    const int w = tid >> 5;
    const int lane = tid & 31;
    const int gr = lane >> 2;
    const int tg = lane & 3;
    const int qbase = qblk * 128;

    // stage Q tile (half, row-major [128][64])
    {
        const int row = tid >> 1, seg = tid & 1;
        const __half* src = qkvh + ((size_t)(b * SS + qbase + row)) * (3 * DD) + h * DK + seg * 32;
        uint4* dst = (uint4*)(sQ + row * AST + seg * 16);
        const uint4* s4 = (const uint4*)src;
#pragma unroll
        for (int i = 0; i < 4; i++) dst[i] = s4[i];
    }
    __syncthreads();

    // Q A-fragments: 4 k-chunks of 16 halves
    uint32_t qa[4][4];
    {
        const uint32_t* qw = sQ + (w * 16) * AST;
#pragma unroll
        for (int c = 0; c < 4; c++) {
            qa[c][0] = qw[gr * AST + 8 * c + tg];
            qa[c][1] = qw[(gr + 8) * AST + 8 * c + tg];
            qa[c][2] = qw[gr * AST + 8 * c + tg + 4];
            qa[c][3] = qw[(gr + 8) * AST + 8 * c + tg + 4];
        }
    }

    float o[8][4];
#pragma unroll
    for (int nd = 0; nd < 8; nd++)
#pragma unroll
        for (int e = 0; e < 4; e++) o[nd][e] = 0.f;
    float m0 = -1e30f, m1 = -1e30f, l0 = 0.f, l1 = 0.f;

    const int ntiles = 2 * qblk + 2;
    const int wrow_min = qbase + w * 16;

    for (int kt = 0; kt < ntiles; kt++) {
        __syncthreads();
        // load K tile [64 keys][64 dims] and V transposed [64 dims][64 keys]
        {
            const int row = tid >> 2, seg = tid & 3;
            const __half* kb = qkvh + ((size_t)(b * SS + kt * 64 + row)) * (3 * DD)
                             + DD + h * DK + seg * 16;
            uint4* dk = (uint4*)(sK + row * AST + seg * 8);
            dk[0] = ((const uint4*)kb)[0];
            dk[1] = ((const uint4*)kb)[1];

            const __half* vb = kb + DD;
            __half tmp[16];
            *(uint4*)tmp       = ((const uint4*)vb)[0];
            *(uint4*)(tmp + 8) = ((const uint4*)vb)[1];
            __half* vt = (__half*)sVt;
#pragma unroll
            for (int i = 0; i < 16; i++)
                vt[(seg * 16 + i) * (2 * AST) + row] = tmp[i];
        }
        __syncthreads();

        if (kt * 64 > wrow_min + 15) continue;

        // S = Q K^T (fp16), scale 1/8
        float s[8][4];
#pragma unroll
        for (int nb = 0; nb < 8; nb++) {
            s[nb][0] = s[nb][1] = s[nb][2] = s[nb][3] = 0.f;
#pragma unroll
            for (int c = 0; c < 4; c++) {
                const uint32_t* kr = sK + (nb * 8 + gr) * AST + 8 * c + tg;
                mma16h(s[nb], qa[c][0], qa[c][1], qa[c][2], qa[c][3], kr[0], kr[4]);
            }
#pragma unroll
            for (int e = 0; e < 4; e++) s[nb][e] *= INV_SCALE;
        }

        const int row0 = wrow_min + gr;
        const int row1 = row0 + 8;
        if (kt * 64 + 63 > wrow_min) {
#pragma unroll
            for (int nb = 0; nb < 8; nb++) {
                const int col = kt * 64 + nb * 8 + 2 * tg;
                if (col > row0)     s[nb][0] = -1e30f;
                if (col + 1 > row0) s[nb][1] = -1e30f;
                if (col > row1)     s[nb][2] = -1e30f;
                if (col + 1 > row1) s[nb][3] = -1e30f;
            }
        }

        // online softmax
        float lm0 = -1e30f, lm1 = -1e30f;
#pragma unroll
        for (int nb = 0; nb < 8; nb++) {
            lm0 = fmaxf(lm0, fmaxf(s[nb][0], s[nb][1]));
            lm1 = fmaxf(lm1, fmaxf(s[nb][2], s[nb][3]));
        }
        lm0 = fmaxf(lm0, __shfl_xor_sync(0xffffffffu, lm0, 1));
        lm0 = fmaxf(lm0, __shfl_xor_sync(0xffffffffu, lm0, 2));
        lm1 = fmaxf(lm1, __shfl_xor_sync(0xffffffffu, lm1, 1));
        lm1 = fmaxf(lm1, __shfl_xor_sync(0xffffffffu, lm1, 2));
        const float nm0 = fmaxf(m0, lm0), nm1 = fmaxf(m1, lm1);
        const float c0 = __expf(m0 - nm0), c1 = __expf(m1 - nm1);
        m0 = nm0; m1 = nm1;

        float ps0 = 0.f, ps1 = 0.f;
#pragma unroll
        for (int nb = 0; nb < 8; nb++) {
            s[nb][0] = __expf(s[nb][0] - m0);
            s[nb][1] = __expf(s[nb][1] - m0);
            s[nb][2] = __expf(s[nb][2] - m1);
            s[nb][3] = __expf(s[nb][3] - m1);
            ps0 += s[nb][0] + s[nb][1];
            ps1 += s[nb][2] + s[nb][3];
        }
        ps0 += __shfl_xor_sync(0xffffffffu, ps0, 1);
        ps0 += __shfl_xor_sync(0xffffffffu, ps0, 2);
        ps1 += __shfl_xor_sync(0xffffffffu, ps1, 1);
        ps1 += __shfl_xor_sync(0xffffffffu, ps1, 2);
        l0 = l0 * c0 + ps0;
        l1 = l1 * c1 + ps1;
#pragma unroll
        for (int nd = 0; nd < 8; nd++) {
            o[nd][0] *= c0; o[nd][1] *= c0;
            o[nd][2] *= c1; o[nd][3] *= c1;
        }

        // P -> fp16 register fragments
        uint32_t p01[8], p23[8];
#pragma unroll
        for (int nb = 0; nb < 8; nb++) {
            p01[nb] = h2u(__floats2half2_rn(s[nb][0], s[nb][1]));
            p23[nb] = h2u(__floats2half2_rn(s[nb][2], s[nb][3]));
        }

        // O += P V (B from transposed V tile)
#pragma unroll
        for (int c = 0; c < 4; c++) {
            const uint32_t a0 = p01[2 * c], a1 = p23[2 * c];
            const uint32_t a2 = p01[2 * c + 1], a3 = p23[2 * c + 1];
#pragma unroll
            for (int nd = 0; nd < 8; nd++) {
                const uint32_t* vr = sVt + (nd * 8 + gr) * AST + 8 * c + tg;
                mma16h(o[nd], a0, a1, a2, a3, vr[0], vr[4]);
            }
        }
    }

    // epilogue: normalize + half store
    const float il0 = 1.f / l0, il1 = 1.f / l1;
    const int grow0 = b * SS + qbase + w * 16 + gr;
    __half* d0 = outh + (size_t)grow0 * DD + h * DK;
    __half* d1 = d0 + 8 * DD;
#pragma unroll
    for (int nd = 0; nd < 8; nd++) {
        *(__half2*)(d0 + nd * 8 + 2 * tg) = __floats2half2_rn(o[nd][0] * il0, o[nd][1] * il0);
        *(__half2*)(d1 + nd * 8 + 2 * tg) = __floats2half2_rn(o[nd][2] * il1, o[nd][3] * il1);
    }
}

// ---------------- LayerNorm: warp-per-row (8 rows/block, shuffle-only) ------
__global__ __launch_bounds__(256)
void ln_kernel(const float* __restrict__ in, const float* __restrict__ gamma,
               const float* __restrict__ beta, float* __restrict__ out,
               __half* __restrict__ outh)
{
    const int wid = threadIdx.x >> 5;
    const int lane = threadIdx.x & 31;
    const int row = blockIdx.x * 8 + wid;
    const float* xr = in + (size_t)row * DD + lane * 16;

    float4 v[4];
#pragma unroll
    for (int i = 0; i < 4; i++) v[i] = *(const float4*)(xr + i * 4);

    float s = 0.f, sq = 0.f;
#pragma unroll
    for (int i = 0; i < 4; i++) {
        s  += v[i].x + v[i].y + v[i].z + v[i].w;
        sq += v[i].x * v[i].x + v[i].y * v[i].y + v[i].z * v[i].z + v[i].w * v[i].w;
    }
#pragma unroll
    for (int off = 16; off > 0; off >>= 1) {
        s  += __shfl_xor_sync(0xffffffffu, s,  off);
        sq += __shfl_xor_sync(0xffffffffu, sq, off);
    }

    const float mean = s * (1.f / DD);
    const float var  = sq * (1.f / DD) - mean * mean;
    const float rstd = rsqrtf(var + EPS);

    const float* gp = gamma + lane * 16;
    const float* bp = beta + lane * 16;
    float* op = out + (size_t)row * DD + lane * 16;
    __half* hp = outh + (size_t)row * DD + lane * 16;

#pragma unroll
    for (int i = 0; i < 4; i++) {
        const float4 gv = *(const float4*)(gp + i * 4);
        const float4 bv = *(const float4*)(bp + i * 4);
        float4 r;
        r.x = (v[i].x - mean) * rstd * gv.x + bv.x;
        r.y = (v[i].y - mean) * rstd * gv.y + bv.y;
        r.z = (v[i].z - mean) * rstd * gv.z + bv.z;
        r.w = (v[i].w - mean) * rstd * gv.w + bv.w;
        *(float4*)(op + i * 4) = r;
        *(__half2*)(hp + i * 4)     = __floats2half2_rn(r.x, r.y);
        *(__half2*)(hp + i * 4 + 2) = __floats2half2_rn(r.z, r.w);
    }
}

// ---------------- driver ----------------
extern "C" void kernel_launch(void* const* d_in, const int* in_sizes, int n_in,
                              void* d_out, int out_size)
{
    const float* x      = (const float*)d_in[0];
    const float* qkv_w  = (const float*)d_in[1];
    const float* qkv_b  = (const float*)d_in[2];
    const float* out_w  = (const float*)d_in[3];
    const float* out_b  = (const float*)d_in[4];
    const float* ln1_g  = (const float*)d_in[5];
    const float* ln1_b  = (const float*)d_in[6];
    const float* mlp_w1 = (const float*)d_in[7];
    const float* mlp_b1 = (const float*)d_in[8];
    const float* mlp_w2 = (const float*)d_in[9];
    const float* mlp_b2 = (const float*)d_in[10];
    const float* ln2_g  = (const float*)d_in[11];
    const float* ln2_b  = (const float*)d_in[12];
    float* outp = (float*)d_out;

    float *px, *pt2;
    __half *pxh, *pqkvh, *pattnh, *phh, *pqkvwt, *poutwt, *pw1t, *pw2t;
    cudaGetSymbolAddress((void**)&px,    g_x);
    cudaGetSymbolAddress((void**)&pxh,   g_xh);
    cudaGetSymbolAddress((void**)&pqkvh, g_qkvh);
    cudaGetSymbolAddress((void**)&pattnh,g_attnh);
    cudaGetSymbolAddress((void**)&phh,   g_hh);
    cudaGetSymbolAddress((void**)&pt2,   g_t2);
    cudaGetSymbolAddress((void**)&pqkvwt,g_qkv_wt);
    cudaGetSymbolAddress((void**)&poutwt,g_out_wt);
    cudaGetSymbolAddress((void**)&pw1t,  g_w1t);
    cudaGetSymbolAddress((void**)&pw2t,  g_w2t);

    cudaFuncSetAttribute(tc_gemm<false,false,true>, cudaFuncAttributeMaxDynamicSharedMemorySize, GSMEM_BYTES);
    cudaFuncSetAttribute(tc_gemm<false,true,false>, cudaFuncAttributeMaxDynamicSharedMemorySize, GSMEM_BYTES);
    cudaFuncSetAttribute(tc_gemm<true,false,true>,  cudaFuncAttributeMaxDynamicSharedMemorySize, GSMEM_BYTES);

    transpose_h<<<dim3(3*DD/32, DD/32, LL), dim3(32,8)>>>(qkv_w, pqkvwt, DD, 3*DD);
    transpose_h<<<dim3(DD/32,   DD/32, LL), dim3(32,8)>>>(out_w, poutwt, DD, DD);
    transpose_h<<<dim3(DFF/32,  DD/32, LL), dim3(32,8)>>>(mlp_w1, pw1t, DD, DFF);
    transpose_h<<<dim3(DD/32,  DFF/32, LL), dim3(32,8)>>>(mlp_w2, pw2t, DFF, DD);

    const int nX = MM * DD;
    copy_half_kernel<<<(nX/4 + 255)/256, 256>>>((const float4*)x, (float4*)px,
                                                (__half2*)pxh, nX/4);

    for (int i = 0; i < LL; i++) {
        // QKV: [8192,512] x [512,1536] (+bias) -> half
        tc_gemm<false,false,true><<<dim3(3*DD/BN, MM/BM), 256, GSMEM_BYTES>>>(
            pxh, pqkvwt + (size_t)i * 3*DD*DD, qkv_b + (size_t)i * 3*DD,
            nullptr, pqkvh, MM, 3*DD, DD);

        attn_h_kernel<<<dim3(SS/128, HH, BB), 256>>>(pqkvh, pattnh);

        // out-proj + residual(x) -> fp32 t2
        tc_gemm<false,true,false><<<dim3(DD/BN, MM/BM), 256, GSMEM_BYTES>>>(
            pattnh, poutwt + (size_t)i * DD*DD, out_b + (size_t)i * DD,
            px, pt2, MM, DD, DD);

        ln_kernel<<<MM/8, 256>>>(pt2, ln1_g + (size_t)i * DD, ln1_b + (size_t)i * DD, px, pxh);

        // MLP1 + ReLU -> half hh
        tc_gemm<true,false,true><<<dim3(DFF/BN, MM/BM), 256, GSMEM_BYTES>>>(
            pxh, pw1t + (size_t)i * DFF*DD, mlp_b1 + (size_t)i * DFF,
            nullptr, phh, MM, DFF, DD);

        // MLP2 + residual(x) -> fp32 t2
        tc_gemm<false,true,false><<<dim3(DD/BN, MM/BM), 256, GSMEM_BYTES>>>(
            phh, pw2t + (size_t)i * DD*DFF, mlp_b2 + (size_t)i * DD,
            px, pt2, MM, DD, DFF);

        float* lnout = (i == LL - 1) ? outp : px;
        ln_kernel<<<MM/8, 256>>>(pt2, ln2_g + (size_t)i * DD, ln2_b + (size_t)i * DD, lnout, pxh);
    }
}

// round 14
// speedup vs baseline: 1.4648x; 1.0493x over previous
#include <cuda_runtime.h>
#include <cuda_fp16.h>
#include <math.h>
#include <cstdint>

// Problem constants
#define BB 8
#define SS 1024
#define DD 512
#define HH 8
#define DK 64
#define DFF 2048
#define LL 6
#define MM (BB*SS)          // 8192 rows
#define EPS 1e-5f
#define INV_SCALE 0.125f

// fp16 GEMM tiling: 128x128 CTA tile, K-chunk 32 halves, 3-stage pipeline
#define BM 128
#define BN 128
#define BKC 32
#define ROW_U32 20                      // 16 data u32 + 4 pad (conflict-free)
#define TILE_U32 (128*ROW_U32)          // 2560
#define TILE_BYTES_H (TILE_U32*4)       // 10240
#define NSTAGE 3
#define GSMEM_BYTES (NSTAGE*2*TILE_BYTES_H)  // 61440

// fp16 attention smem strides (u32 units)
#define AST 36                          // 72 halves per row (64 data + 8 pad)

// ---------------- scratch ----------------
__device__ float  g_x[MM*DD];           // exact fp32 activations
__device__ __half g_xh[MM*DD];          // half copy (GEMM A operand)
__device__ __half g_qkvh[MM*3*DD];      // QKV in half
__device__ __half g_attnh[MM*DD];       // attention output (half)
__device__ __half g_hh[MM*DFF];         // MLP hidden (half)
__device__ float  g_t2[MM*DD];
// transposed half weights, [N,K] K-major
__device__ __half g_qkv_wt[LL*3*DD*DD];
__device__ __half g_out_wt[LL*DD*DD];
__device__ __half g_w1t[LL*DFF*DD];
__device__ __half g_w2t[LL*DD*DFF];

// ---------------- helpers ----------------
__device__ __forceinline__ uint32_t smem_u32(const void* p) {
    uint32_t a;
    asm("{ .reg .u64 t; cvta.to.shared.u64 t, %1; cvt.u32.u64 %0, t; }" : "=r"(a) : "l"(p));
    return a;
}
__device__ __forceinline__ void cp_async16(uint32_t dst, const void* src) {
    asm volatile("cp.async.cg.shared.global [%0], [%1], 16;" :: "r"(dst), "l"(src));
}
__device__ __forceinline__ void cp_commit() {
    asm volatile("cp.async.commit_group;" ::: "memory");
}
__device__ __forceinline__ void mma16h(float c[4], uint32_t a0, uint32_t a1,
                                       uint32_t a2, uint32_t a3,
                                       uint32_t b0, uint32_t b1) {
    asm volatile(
        "mma.sync.aligned.m16n8k16.row.col.f32.f16.f16.f32 "
        "{%0,%1,%2,%3}, {%4,%5,%6,%7}, {%8,%9}, {%0,%1,%2,%3};"
        : "+f"(c[0]), "+f"(c[1]), "+f"(c[2]), "+f"(c[3])
        : "r"(a0), "r"(a1), "r"(a2), "r"(a3), "r"(b0), "r"(b1));
}
__device__ __forceinline__ uint32_t h2u(__half2 h) { return *(uint32_t*)&h; }

// ---------------- elementwise ----------------
__global__ void copy_half_kernel(const float4* __restrict__ src, float4* __restrict__ dst,
                                 __half2* __restrict__ dsth, int n4) {
    int i = blockIdx.x * blockDim.x + threadIdx.x;
    if (i < n4) {
        float4 v = src[i];
        dst[i] = v;
        dsth[2*i]   = __floats2half2_rn(v.x, v.y);
        dsth[2*i+1] = __floats2half2_rn(v.z, v.w);
    }
}

// transpose + fp16 convert: W[L][K][N] -> Wt[L][N][K]
__global__ void transpose_h(const float* __restrict__ W, __half* __restrict__ Wt,
                            int K, int N) {
    __shared__ float t[32][33];
    const int l = blockIdx.z;
    const float* Wl = W + (size_t)l * K * N;
    __half* Wtl = Wt + (size_t)l * K * N;
    const int k0 = blockIdx.y * 32, n0 = blockIdx.x * 32;
    const int tx = threadIdx.x, ty = threadIdx.y;
#pragma unroll
    for (int i = 0; i < 32; i += 8)
        t[ty + i][tx] = Wl[(size_t)(k0 + ty + i) * N + n0 + tx];
    __syncthreads();
#pragma unroll
    for (int i = 0; i < 32; i += 8)
        Wtl[(size_t)(n0 + ty + i) * K + k0 + tx] = __float2half(t[tx][ty + i]);
}

// ---------------- fp16 mma GEMM: C[M,N] = A[M,K] @ Wt[N,K]^T ----------
// Round-9 structure (scalar LDS fragments, two syncs/chunk), 3-stage ring.
template<bool RELU, bool RESID, bool HOUT>
__global__ __launch_bounds__(256)
void tc_gemm(const __half* __restrict__ A, const __half* __restrict__ Bw,
             const float* __restrict__ bias, const float* __restrict__ resid,
             void* __restrict__ Cv, int M, int N, int K)
{
    extern __shared__ float smemf[];
    const uint32_t sb = smem_u32(smemf);

    const int tid = threadIdx.x;
    const int wid = tid >> 5;
    const int lane = tid & 31;
    const int bx = blockIdx.x, by = blockIdx.y;

    const __half* Ag = A + (size_t)by * BM * K;
    const __half* Bg = Bw + (size_t)bx * BN * K;

    auto issue_chunk = [&](int chunk, int buf) {
        const int k0 = chunk * BKC;
        const uint32_t base = sb + (uint32_t)buf * (2u * TILE_BYTES_H);
#pragma unroll
        for (int p = 0; p < 2; p++) {
            const int idx = tid * 2 + p;
            const int row = idx >> 2;
            const int j = idx & 3;
            cp_async16(base + (uint32_t)row * (ROW_U32*4) + (uint32_t)j * 16,
                       Ag + (size_t)row * K + k0 + j * 8);
        }
#pragma unroll
        for (int p = 0; p < 2; p++) {
            const int idx = tid * 2 + p;
            const int row = idx >> 2;
            const int j = idx & 3;
            cp_async16(base + TILE_BYTES_H + (uint32_t)row * (ROW_U32*4) + (uint32_t)j * 16,
                       Bg + (size_t)row * K + k0 + j * 8);
        }
        cp_commit();
    };

    const int nc = K / BKC;        // 16 or 64 (always >= 3)
    issue_chunk(0, 0);
    issue_chunk(1, 1);
    issue_chunk(2, 2);

    const int wm = (wid >> 2) * 64;
    const int wn = (wid & 3) * 32;
    const int qr = lane >> 2;
    const int qc = lane & 3;

    float acc[4][4][4];
#pragma unroll
    for (int mi = 0; mi < 4; mi++)
#pragma unroll
        for (int ni = 0; ni < 4; ni++)
#pragma unroll
            for (int e = 0; e < 4; e++) acc[mi][ni][e] = 0.f;

    int buf = 0;
    for (int c = 0; c < nc; c++) {
        const int ahead = nc - 1 - c;
        if (ahead >= 2)      asm volatile("cp.async.wait_group 2;" ::: "memory");
        else if (ahead == 1) asm volatile("cp.async.wait_group 1;" ::: "memory");
        else                 asm volatile("cp.async.wait_group 0;" ::: "memory");
        __syncthreads();

        const uint32_t* sAu = reinterpret_cast<const uint32_t*>(smemf) + buf * (2 * TILE_U32);
        const uint32_t* sBu = sAu + TILE_U32;

#pragma unroll
        for (int ks = 0; ks < 2; ks++) {
            const int col = ks * 8 + qc;
            uint32_t bfr[4][2];
#pragma unroll
            for (int ni = 0; ni < 4; ni++) {
                const int n = wn + ni * 8 + qr;
                bfr[ni][0] = sBu[n * ROW_U32 + col];
                bfr[ni][1] = sBu[n * ROW_U32 + col + 4];
            }
#pragma unroll
            for (int mi = 0; mi < 4; mi++) {
                const int r = wm + mi * 16 + qr;
                const uint32_t a0 = sAu[r * ROW_U32 + col];
                const uint32_t a1 = sAu[(r + 8) * ROW_U32 + col];
                const uint32_t a2 = sAu[r * ROW_U32 + col + 4];
                const uint32_t a3 = sAu[(r + 8) * ROW_U32 + col + 4];
#pragma unroll
                for (int ni = 0; ni < 4; ni++)
                    mma16h(acc[mi][ni], a0, a1, a2, a3, bfr[ni][0], bfr[ni][1]);
            }
        }
        __syncthreads();
        if (c + 3 < nc) issue_chunk(c + 3, buf);
        buf = (buf == NSTAGE - 1) ? 0 : buf + 1;
    }

#pragma unroll
    for (int mi = 0; mi < 4; mi++) {
#pragma unroll
        for (int ni = 0; ni < 4; ni++) {
            const int r0 = by * BM + wm + mi * 16 + qr;
            const int c0 = bx * BN + wn + ni * 8 + qc * 2;
            const float2 bv = *(const float2*)(bias + c0);
#pragma unroll
            for (int hrow = 0; hrow < 2; hrow++) {
                const int rr = r0 + hrow * 8;
                float v0 = acc[mi][ni][hrow * 2 + 0] + bv.x;
                float v1 = acc[mi][ni][hrow * 2 + 1] + bv.y;
                if (RESID) {
                    const float2 rv = *(const float2*)(resid + (size_t)rr * N + c0);
                    v0 += rv.x; v1 += rv.y;
                }
                if (RELU) { v0 = fmaxf(v0, 0.f); v1 = fmaxf(v1, 0.f); }
                if (HOUT) {
                    *(__half2*)((__half*)Cv + (size_t)rr * N + c0) = __floats2half2_rn(v0, v1);
                } else {
                    *(float2*)((float*)Cv + (size_t)rr * N + c0) = make_float2(v0, v1);
                }
            }
        }
    }
}

// ---------------- flash attention, full fp16 mma (round-9 proven form) ------
__global__ __launch_bounds__(256, 1)
void attn_h_kernel(const __half* __restrict__ qkvh, __half* __restrict__ outh)
{
    __shared__ uint32_t sQ[128*AST];    // 18432 B
    __shared__ uint32_t sK[64*AST];     //  9216 B
    __shared__ uint32_t sVt[64*AST];    //  9216 B (V transposed: [d][key])

    const int qblk = blockIdx.x;
    const int h = blockIdx.y;
    const int b = blockIdx.z;
    const int tid = threadIdx.x;
    const int w = tid >> 5;
    const int lane = tid & 31;
    const int gr = lane >> 2;
    const int tg = lane & 3;
    const int qbase = qblk * 128;

    // stage Q tile (half, row-major [128][64])
    {
        const int row = tid >> 1, seg = tid & 1;
        const __half* src = qkvh + ((size_t)(b * SS + qbase + row)) * (3 * DD) + h * DK + seg * 32;
        uint4* dst = (uint4*)(sQ + row * AST + seg * 16);
        const uint4* s4 = (const uint4*)src;
#pragma unroll
        for (int i = 0; i < 4; i++) dst[i] = s4[i];
    }
    __syncthreads();

    // Q A-fragments: 4 k-chunks of 16 halves
    uint32_t qa[4][4];
    {
        const uint32_t* qw = sQ + (w * 16) * AST;
#pragma unroll
        for (int c = 0; c < 4; c++) {
            qa[c][0] = qw[gr * AST + 8 * c + tg];
            qa[c][1] = qw[(gr + 8) * AST + 8 * c + tg];
            qa[c][2] = qw[gr * AST + 8 * c + tg + 4];
            qa[c][3] = qw[(gr + 8) * AST + 8 * c + tg + 4];
        }
    }

    float o[8][4];
#pragma unroll
    for (int nd = 0; nd < 8; nd++)
#pragma unroll
        for (int e = 0; e < 4; e++) o[nd][e] = 0.f;
    float m0 = -1e30f, m1 = -1e30f, l0 = 0.f, l1 = 0.f;

    const int ntiles = 2 * qblk + 2;
    const int wrow_min = qbase + w * 16;

    for (int kt = 0; kt < ntiles; kt++) {
        __syncthreads();
        // load K tile [64 keys][64 dims] and V transposed [64 dims][64 keys]
        {
            const int row = tid >> 2, seg = tid & 3;
            const __half* kb = qkvh + ((size_t)(b * SS + kt * 64 + row)) * (3 * DD)
                             + DD + h * DK + seg * 16;
            uint4* dk = (uint4*)(sK + row * AST + seg * 8);
            dk[0] = ((const uint4*)kb)[0];
            dk[1] = ((const uint4*)kb)[1];

            const __half* vb = kb + DD;
            __half tmp[16];
            *(uint4*)tmp       = ((const uint4*)vb)[0];
            *(uint4*)(tmp + 8) = ((const uint4*)vb)[1];
            __half* vt = (__half*)sVt;
#pragma unroll
            for (int i = 0; i < 16; i++)
                vt[(seg * 16 + i) * (2 * AST) + row] = tmp[i];
        }
        __syncthreads();

        if (kt * 64 > wrow_min + 15) continue;

        // S = Q K^T (fp16), scale 1/8
        float s[8][4];
#pragma unroll
        for (int nb = 0; nb < 8; nb++) {
            s[nb][0] = s[nb][1] = s[nb][2] = s[nb][3] = 0.f;
#pragma unroll
            for (int c = 0; c < 4; c++) {
                const uint32_t* kr = sK + (nb * 8 + gr) * AST + 8 * c + tg;
                mma16h(s[nb], qa[c][0], qa[c][1], qa[c][2], qa[c][3], kr[0], kr[4]);
            }
#pragma unroll
            for (int e = 0; e < 4; e++) s[nb][e] *= INV_SCALE;
        }

        const int row0 = wrow_min + gr;
        const int row1 = row0 + 8;
        if (kt * 64 + 63 > wrow_min) {
#pragma unroll
            for (int nb = 0; nb < 8; nb++) {
                const int col = kt * 64 + nb * 8 + 2 * tg;
                if (col > row0)     s[nb][0] = -1e30f;
                if (col + 1 > row0) s[nb][1] = -1e30f;
                if (col > row1)     s[nb][2] = -1e30f;
                if (col + 1 > row1) s[nb][3] = -1e30f;
            }
        }

        // online softmax
        float lm0 = -1e30f, lm1 = -1e30f;
#pragma unroll
        for (int nb = 0; nb < 8; nb++) {
            lm0 = fmaxf(lm0, fmaxf(s[nb][0], s[nb][1]));
            lm1 = fmaxf(lm1, fmaxf(s[nb][2], s[nb][3]));
        }
        lm0 = fmaxf(lm0, __shfl_xor_sync(0xffffffffu, lm0, 1));
        lm0 = fmaxf(lm0, __shfl_xor_sync(0xffffffffu, lm0, 2));
        lm1 = fmaxf(lm1, __shfl_xor_sync(0xffffffffu, lm1, 1));
        lm1 = fmaxf(lm1, __shfl_xor_sync(0xffffffffu, lm1, 2));
        const float nm0 = fmaxf(m0, lm0), nm1 = fmaxf(m1, lm1);
        const float c0 = __expf(m0 - nm0), c1 = __expf(m1 - nm1);
        m0 = nm0; m1 = nm1;

        float ps0 = 0.f, ps1 = 0.f;
#pragma unroll
        for (int nb = 0; nb < 8; nb++) {
            s[nb][0] = __expf(s[nb][0] - m0);
            s[nb][1] = __expf(s[nb][1] - m0);
            s[nb][2] = __expf(s[nb][2] - m1);
            s[nb][3] = __expf(s[nb][3] - m1);
            ps0 += s[nb][0] + s[nb][1];
            ps1 += s[nb][2] + s[nb][3];
        }
        ps0 += __shfl_xor_sync(0xffffffffu, ps0, 1);
        ps0 += __shfl_xor_sync(0xffffffffu, ps0, 2);
        ps1 += __shfl_xor_sync(0xffffffffu, ps1, 1);
        ps1 += __shfl_xor_sync(0xffffffffu, ps1, 2);
        l0 = l0 * c0 + ps0;
        l1 = l1 * c1 + ps1;
#pragma unroll
        for (int nd = 0; nd < 8; nd++) {
            o[nd][0] *= c0; o[nd][1] *= c0;
            o[nd][2] *= c1; o[nd][3] *= c1;
        }

        // P -> fp16 register fragments
        uint32_t p01[8], p23[8];
#pragma unroll
        for (int nb = 0; nb < 8; nb++) {
            p01[nb] = h2u(__floats2half2_rn(s[nb][0], s[nb][1]));
            p23[nb] = h2u(__floats2half2_rn(s[nb][2], s[nb][3]));
        }

        // O += P V (B from transposed V tile)
#pragma unroll
        for (int c = 0; c < 4; c++) {
            const uint32_t a0 = p01[2 * c], a1 = p23[2 * c];
            const uint32_t a2 = p01[2 * c + 1], a3 = p23[2 * c + 1];
#pragma unroll
            for (int nd = 0; nd < 8; nd++) {
                const uint32_t* vr = sVt + (nd * 8 + gr) * AST + 8 * c + tg;
                mma16h(o[nd], a0, a1, a2, a3, vr[0], vr[4]);
            }
        }
    }

    // epilogue: normalize + half store
    const float il0 = 1.f / l0, il1 = 1.f / l1;
    const int grow0 = b * SS + qbase + w * 16 + gr;
    __half* d0 = outh + (size_t)grow0 * DD + h * DK;
    __half* d1 = d0 + 8 * DD;
#pragma unroll
    for (int nd = 0; nd < 8; nd++) {
        *(__half2*)(d0 + nd * 8 + 2 * tg) = __floats2half2_rn(o[nd][0] * il0, o[nd][1] * il0);
        *(__half2*)(d1 + nd * 8 + 2 * tg) = __floats2half2_rn(o[nd][2] * il1, o[nd][3] * il1);
    }
}

// ---------------- LayerNorm: warp-per-row, COALESCED (lane-interleaved) -----
// lane handles float4s at indices lane + 32*i  ->  each warp load/store
// instruction covers 512 contiguous bytes. Shuffle-only reduction.
__global__ __launch_bounds__(256)
void ln_kernel(const float* __restrict__ in, const float* __restrict__ gamma,
               const float* __restrict__ beta, float* __restrict__ out,
               __half* __restrict__ outh)
{
    const int wid = threadIdx.x >> 5;
    const int lane = threadIdx.x & 31;
    const int row = blockIdx.x * 8 + wid;
    const float4* xr = (const float4*)(in + (size_t)row * DD);

    float4 v[4];
#pragma unroll
    for (int i = 0; i < 4; i++) v[i] = xr[lane + 32 * i];

    float s = 0.f, sq = 0.f;
#pragma unroll
    for (int i = 0; i < 4; i++) {
        s  += v[i].x + v[i].y + v[i].z + v[i].w;
        sq += v[i].x * v[i].x + v[i].y * v[i].y + v[i].z * v[i].z + v[i].w * v[i].w;
    }
#pragma unroll
    for (int off = 16; off > 0; off >>= 1) {
        s  += __shfl_xor_sync(0xffffffffu, s,  off);
        sq += __shfl_xor_sync(0xffffffffu, sq, off);
    }

    const float mean = s * (1.f / DD);
    const float var  = sq * (1.f / DD) - mean * mean;
    const float rstd = rsqrtf(var + EPS);

    const float4* gp = (const float4*)gamma;
    const float4* bp = (const float4*)beta;
    float4* op = (float4*)(out + (size_t)row * DD);
    __half2* hp = (__half2*)(outh + (size_t)row * DD);

#pragma unroll
    for (int i = 0; i < 4; i++) {
        const int idx = lane + 32 * i;
        const float4 gv = gp[idx];
        const float4 bv = bp[idx];
        float4 r;
        r.x = (v[i].x - mean) * rstd * gv.x + bv.x;
        r.y = (v[i].y - mean) * rstd * gv.y + bv.y;
        r.z = (v[i].z - mean) * rstd * gv.z + bv.z;
        r.w = (v[i].w - mean) * rstd * gv.w + bv.w;
        op[idx] = r;
        hp[2 * idx]     = __floats2half2_rn(r.x, r.y);
        hp[2 * idx + 1] = __floats2half2_rn(r.z, r.w);
    }
}

// ---------------- driver ----------------
extern "C" void kernel_launch(void* const* d_in, const int* in_sizes, int n_in,
                              void* d_out, int out_size)
{
    const float* x      = (const float*)d_in[0];
    const float* qkv_w  = (const float*)d_in[1];
    const float* qkv_b  = (const float*)d_in[2];
    const float* out_w  = (const float*)d_in[3];
    const float* out_b  = (const float*)d_in[4];
    const float* ln1_g  = (const float*)d_in[5];
    const float* ln1_b  = (const float*)d_in[6];
    const float* mlp_w1 = (const float*)d_in[7];
    const float* mlp_b1 = (const float*)d_in[8];
    const float* mlp_w2 = (const float*)d_in[9];
    const float* mlp_b2 = (const float*)d_in[10];
    const float* ln2_g  = (const float*)d_in[11];
    const float* ln2_b  = (const float*)d_in[12];
    float* outp = (float*)d_out;

    float *px, *pt2;
    __half *pxh, *pqkvh, *pattnh, *phh, *pqkvwt, *poutwt, *pw1t, *pw2t;
    cudaGetSymbolAddress((void**)&px,    g_x);
    cudaGetSymbolAddress((void**)&pxh,   g_xh);
    cudaGetSymbolAddress((void**)&pqkvh, g_qkvh);
    cudaGetSymbolAddress((void**)&pattnh,g_attnh);
    cudaGetSymbolAddress((void**)&phh,   g_hh);
    cudaGetSymbolAddress((void**)&pt2,   g_t2);
    cudaGetSymbolAddress((void**)&pqkvwt,g_qkv_wt);
    cudaGetSymbolAddress((void**)&poutwt,g_out_wt);
    cudaGetSymbolAddress((void**)&pw1t,  g_w1t);
    cudaGetSymbolAddress((void**)&pw2t,  g_w2t);

    cudaFuncSetAttribute(tc_gemm<false,false,true>, cudaFuncAttributeMaxDynamicSharedMemorySize, GSMEM_BYTES);
    cudaFuncSetAttribute(tc_gemm<false,true,false>, cudaFuncAttributeMaxDynamicSharedMemorySize, GSMEM_BYTES);
    cudaFuncSetAttribute(tc_gemm<true,false,true>,  cudaFuncAttributeMaxDynamicSharedMemorySize, GSMEM_BYTES);

    transpose_h<<<dim3(3*DD/32, DD/32, LL), dim3(32,8)>>>(qkv_w, pqkvwt, DD, 3*DD);
    transpose_h<<<dim3(DD/32,   DD/32, LL), dim3(32,8)>>>(out_w, poutwt, DD, DD);
    transpose_h<<<dim3(DFF/32,  DD/32, LL), dim3(32,8)>>>(mlp_w1, pw1t, DD, DFF);
    transpose_h<<<dim3(DD/32,  DFF/32, LL), dim3(32,8)>>>(mlp_w2, pw2t, DFF, DD);

    const int nX = MM * DD;
    copy_half_kernel<<<(nX/4 + 255)/256, 256>>>((const float4*)x, (float4*)px,
                                                (__half2*)pxh, nX/4);

    for (int i = 0; i < LL; i++) {
        // QKV: [8192,512] x [512,1536] (+bias) -> half
        tc_gemm<false,false,true><<<dim3(3*DD/BN, MM/BM), 256, GSMEM_BYTES>>>(
            pxh, pqkvwt + (size_t)i * 3*DD*DD, qkv_b + (size_t)i * 3*DD,
            nullptr, pqkvh, MM, 3*DD, DD);

        attn_h_kernel<<<dim3(SS/128, HH, BB), 256>>>(pqkvh, pattnh);

        // out-proj + residual(x) -> fp32 t2
        tc_gemm<false,true,false><<<dim3(DD/BN, MM/BM), 256, GSMEM_BYTES>>>(
            pattnh, poutwt + (size_t)i * DD*DD, out_b + (size_t)i * DD,
            px, pt2, MM, DD, DD);

        ln_kernel<<<MM/8, 256>>>(pt2, ln1_g + (size_t)i * DD, ln1_b + (size_t)i * DD, px, pxh);

        // MLP1 + ReLU -> half hh
        tc_gemm<true,false,true><<<dim3(DFF/BN, MM/BM), 256, GSMEM_BYTES>>>(
            pxh, pw1t + (size_t)i * DFF*DD, mlp_b1 + (size_t)i * DFF,
            nullptr, phh, MM, DFF, DD);

        // MLP2 + residual(x) -> fp32 t2
        tc_gemm<false,true,false><<<dim3(DD/BN, MM/BM), 256, GSMEM_BYTES>>>(
            phh, pw2t + (size_t)i * DD*DFF, mlp_b2 + (size_t)i * DD,
            px, pt2, MM, DD, DFF);

        float* lnout = (i == LL - 1) ? outp : px;
        ln_kernel<<<MM/8, 256>>>(pt2, ln2_g + (size_t)i * DD, ln2_b + (size_t)i * DD, lnout, pxh);
    }
}

// round 15
// speedup vs baseline: 1.5026x; 1.0258x over previous
#include <cuda_runtime.h>
#include <cuda_fp16.h>
#include <math.h>
#include <cstdint>

// Problem constants
#define BB 8
#define SS 1024
#define DD 512
#define HH 8
#define DK 64
#define DFF 2048
#define LL 6
#define MM (BB*SS)          // 8192 rows
#define EPS 1e-5f
#define INV_SCALE 0.125f

// fp16 GEMM tiling: 128x128 CTA tile, K-chunk 32 halves, 3-stage single-sync
#define BM 128
#define BN 128
#define BKC 32
#define ROW_U32 20                      // 16 data u32 + 4 pad (conflict-free)
#define TILE_U32 (128*ROW_U32)          // 2560
#define TILE_BYTES_H (TILE_U32*4)       // 10240
#define NSTAGE 3
#define GSMEM_BYTES (NSTAGE*2*TILE_BYTES_H)  // 61440

// fp16 attention smem strides (u32 units)
#define AST 36                          // 72 halves per row (64 data + 8 pad)

// ---------------- scratch ----------------
__device__ float  g_x[MM*DD];           // exact fp32 activations
__device__ __half g_xh[MM*DD];          // half copy (GEMM A operand)
__device__ __half g_qkvh[MM*3*DD];      // QKV in half
__device__ __half g_attnh[MM*DD];       // attention output (half)
__device__ __half g_hh[MM*DFF];         // MLP hidden (half)
__device__ float  g_t2[MM*DD];
// transposed half weights, [N,K] K-major
__device__ __half g_qkv_wt[LL*3*DD*DD];
__device__ __half g_out_wt[LL*DD*DD];
__device__ __half g_w1t[LL*DFF*DD];
__device__ __half g_w2t[LL*DD*DFF];

// ---------------- helpers ----------------
__device__ __forceinline__ uint32_t smem_u32(const void* p) {
    uint32_t a;
    asm("{ .reg .u64 t; cvta.to.shared.u64 t, %1; cvt.u32.u64 %0, t; }" : "=r"(a) : "l"(p));
    return a;
}
__device__ __forceinline__ void cp_async16(uint32_t dst, const void* src) {
    asm volatile("cp.async.cg.shared.global [%0], [%1], 16;" :: "r"(dst), "l"(src));
}
__device__ __forceinline__ void cp_commit() {
    asm volatile("cp.async.commit_group;" ::: "memory");
}
__device__ __forceinline__ void mma16h(float c[4], uint32_t a0, uint32_t a1,
                                       uint32_t a2, uint32_t a3,
                                       uint32_t b0, uint32_t b1) {
    asm volatile(
        "mma.sync.aligned.m16n8k16.row.col.f32.f16.f16.f32 "
        "{%0,%1,%2,%3}, {%4,%5,%6,%7}, {%8,%9}, {%0,%1,%2,%3};"
        : "+f"(c[0]), "+f"(c[1]), "+f"(c[2]), "+f"(c[3])
        : "r"(a0), "r"(a1), "r"(a2), "r"(a3), "r"(b0), "r"(b1));
}
__device__ __forceinline__ uint32_t h2u(__half2 h) { return *(uint32_t*)&h; }

// ---------------- elementwise ----------------
__global__ void copy_half_kernel(const float4* __restrict__ src, float4* __restrict__ dst,
                                 __half2* __restrict__ dsth, int n4) {
    int i = blockIdx.x * blockDim.x + threadIdx.x;
    if (i < n4) {
        float4 v = src[i];
        dst[i] = v;
        dsth[2*i]   = __floats2half2_rn(v.x, v.y);
        dsth[2*i+1] = __floats2half2_rn(v.z, v.w);
    }
}

// transpose + fp16 convert: W[L][K][N] -> Wt[L][N][K]
__global__ void transpose_h(const float* __restrict__ W, __half* __restrict__ Wt,
                            int K, int N) {
    __shared__ float t[32][33];
    const int l = blockIdx.z;
    const float* Wl = W + (size_t)l * K * N;
    __half* Wtl = Wt + (size_t)l * K * N;
    const int k0 = blockIdx.y * 32, n0 = blockIdx.x * 32;
    const int tx = threadIdx.x, ty = threadIdx.y;
#pragma unroll
    for (int i = 0; i < 32; i += 8)
        t[ty + i][tx] = Wl[(size_t)(k0 + ty + i) * N + n0 + tx];
    __syncthreads();
#pragma unroll
    for (int i = 0; i < 32; i += 8)
        Wtl[(size_t)(n0 + ty + i) * K + k0 + tx] = __float2half(t[tx][ty + i]);
}

// ---------------- fp16 mma GEMM: C[M,N] = A[M,K] @ Wt[N,K]^T ----------
// 3-stage ring, SINGLE __syncthreads per chunk, cp.async issued before compute.
template<bool RELU, bool RESID, bool HOUT>
__global__ __launch_bounds__(256)
void tc_gemm(const __half* __restrict__ A, const __half* __restrict__ Bw,
             const float* __restrict__ bias, const float* __restrict__ resid,
             void* __restrict__ Cv, int M, int N, int K)
{
    extern __shared__ float smemf[];
    const uint32_t sb = smem_u32(smemf);

    const int tid = threadIdx.x;
    const int wid = tid >> 5;
    const int lane = tid & 31;
    const int bx = blockIdx.x, by = blockIdx.y;

    const __half* Ag = A + (size_t)by * BM * K;
    const __half* Bg = Bw + (size_t)bx * BN * K;

    auto issue_chunk = [&](int chunk, int buf) {
        const int k0 = chunk * BKC;
        const uint32_t base = sb + (uint32_t)buf * (2u * TILE_BYTES_H);
#pragma unroll
        for (int p = 0; p < 2; p++) {
            const int idx = tid * 2 + p;
            const int row = idx >> 2;
            const int j = idx & 3;
            cp_async16(base + (uint32_t)row * (ROW_U32*4) + (uint32_t)j * 16,
                       Ag + (size_t)row * K + k0 + j * 8);
        }
#pragma unroll
        for (int p = 0; p < 2; p++) {
            const int idx = tid * 2 + p;
            const int row = idx >> 2;
            const int j = idx & 3;
            cp_async16(base + TILE_BYTES_H + (uint32_t)row * (ROW_U32*4) + (uint32_t)j * 16,
                       Bg + (size_t)row * K + k0 + j * 8);
        }
        cp_commit();
    };

    const int nc = K / BKC;        // 16 or 64 (always >= 3)
    issue_chunk(0, 0);
    issue_chunk(1, 1);

    const int wm = (wid >> 2) * 64;
    const int wn = (wid & 3) * 32;
    const int qr = lane >> 2;
    const int qc = lane & 3;

    float acc[4][4][4];
#pragma unroll
    for (int mi = 0; mi < 4; mi++)
#pragma unroll
        for (int ni = 0; ni < 4; ni++)
#pragma unroll
            for (int e = 0; e < 4; e++) acc[mi][ni][e] = 0.f;

    int buf = 0;      // buffer holding chunk c
    int nbuf = 2;     // buffer for chunk c+2
    for (int c = 0; c < nc; c++) {
        if (c + 1 < nc) asm volatile("cp.async.wait_group 1;" ::: "memory");
        else            asm volatile("cp.async.wait_group 0;" ::: "memory");
        __syncthreads();
        // safe: buffer nbuf == (c+2)%3 == (c-1)%3 whose readers all passed the sync
        if (c + 2 < nc) issue_chunk(c + 2, nbuf);

        const uint32_t* sAu = reinterpret_cast<const uint32_t*>(smemf) + buf * (2 * TILE_U32);
        const uint32_t* sBu = sAu + TILE_U32;

#pragma unroll
        for (int ks = 0; ks < 2; ks++) {
            const int col = ks * 8 + qc;
            uint32_t bfr[4][2];
#pragma unroll
            for (int ni = 0; ni < 4; ni++) {
                const int n = wn + ni * 8 + qr;
                bfr[ni][0] = sBu[n * ROW_U32 + col];
                bfr[ni][1] = sBu[n * ROW_U32 + col + 4];
            }
#pragma unroll
            for (int mi = 0; mi < 4; mi++) {
                const int r = wm + mi * 16 + qr;
                const uint32_t a0 = sAu[r * ROW_U32 + col];
                const uint32_t a1 = sAu[(r + 8) * ROW_U32 + col];
                const uint32_t a2 = sAu[r * ROW_U32 + col + 4];
                const uint32_t a3 = sAu[(r + 8) * ROW_U32 + col + 4];
#pragma unroll
                for (int ni = 0; ni < 4; ni++)
                    mma16h(acc[mi][ni], a0, a1, a2, a3, bfr[ni][0], bfr[ni][1]);
            }
        }
        buf  = (buf  == NSTAGE - 1) ? 0 : buf + 1;
        nbuf = (nbuf == NSTAGE - 1) ? 0 : nbuf + 1;
    }

#pragma unroll
    for (int mi = 0; mi < 4; mi++) {
#pragma unroll
        for (int ni = 0; ni < 4; ni++) {
            const int r0 = by * BM + wm + mi * 16 + qr;
            const int c0 = bx * BN + wn + ni * 8 + qc * 2;
            const float2 bv = *(const float2*)(bias + c0);
#pragma unroll
            for (int hrow = 0; hrow < 2; hrow++) {
                const int rr = r0 + hrow * 8;
                float v0 = acc[mi][ni][hrow * 2 + 0] + bv.x;
                float v1 = acc[mi][ni][hrow * 2 + 1] + bv.y;
                if (RESID) {
                    const float2 rv = *(const float2*)(resid + (size_t)rr * N + c0);
                    v0 += rv.x; v1 += rv.y;
                }
                if (RELU) { v0 = fmaxf(v0, 0.f); v1 = fmaxf(v1, 0.f); }
                if (HOUT) {
                    *(__half2*)((__half*)Cv + (size_t)rr * N + c0) = __floats2half2_rn(v0, v1);
                } else {
                    *(float2*)((float*)Cv + (size_t)rr * N + c0) = make_float2(v0, v1);
                }
            }
        }
    }
}

// ---------------- flash attention, full fp16 mma (round-9 proven form) ------
__global__ __launch_bounds__(256, 1)
void attn_h_kernel(const __half* __restrict__ qkvh, __half* __restrict__ outh)
{
    __shared__ uint32_t sQ[128*AST];    // 18432 B
    __shared__ uint32_t sK[64*AST];     //  9216 B
    __shared__ uint32_t sVt[64*AST];    //  9216 B (V transposed: [d][key])

    const int qblk = blockIdx.x;
    const int h = blockIdx.y;
    const int b = blockIdx.z;
    const int tid = threadIdx.x;
    const int w = tid >> 5;
    const int lane = tid & 31;
    const int gr = lane >> 2;
    const int tg = lane & 3;
    const int qbase = qblk * 128;

    // stage Q tile (half, row-major [128][64])
    {
        const int row = tid >> 1, seg = tid & 1;
        const __half* src = qkvh + ((size_t)(b * SS + qbase + row)) * (3 * DD) + h * DK + seg * 32;
        uint4* dst = (uint4*)(sQ + row * AST + seg * 16);
        const uint4* s4 = (const uint4*)src;
#pragma unroll
        for (int i = 0; i < 4; i++) dst[i] = s4[i];
    }
    __syncthreads();

    // Q A-fragments: 4 k-chunks of 16 halves
    uint32_t qa[4][4];
    {
        const uint32_t* qw = sQ + (w * 16) * AST;
#pragma unroll
        for (int c = 0; c < 4; c++) {
            qa[c][0] = qw[gr * AST + 8 * c + tg];
            qa[c][1] = qw[(gr + 8) * AST + 8 * c + tg];
            qa[c][2] = qw[gr * AST + 8 * c + tg + 4];
            qa[c][3] = qw[(gr + 8) * AST + 8 * c + tg + 4];
        }
    }

    float o[8][4];
#pragma unroll
    for (int nd = 0; nd < 8; nd++)
#pragma unroll
        for (int e = 0; e < 4; e++) o[nd][e] = 0.f;
    float m0 = -1e30f, m1 = -1e30f, l0 = 0.f, l1 = 0.f;

    const int ntiles = 2 * qblk + 2;
    const int wrow_min = qbase + w * 16;

    for (int kt = 0; kt < ntiles; kt++) {
        __syncthreads();
        // load K tile [64 keys][64 dims] and V transposed [64 dims][64 keys]
        {
            const int row = tid >> 2, seg = tid & 3;
            const __half* kb = qkvh + ((size_t)(b * SS + kt * 64 + row)) * (3 * DD)
                             + DD + h * DK + seg * 16;
            uint4* dk = (uint4*)(sK + row * AST + seg * 8);
            dk[0] = ((const uint4*)kb)[0];
            dk[1] = ((const uint4*)kb)[1];

            const __half* vb = kb + DD;
            __half tmp[16];
            *(uint4*)tmp       = ((const uint4*)vb)[0];
            *(uint4*)(tmp + 8) = ((const uint4*)vb)[1];
            __half* vt = (__half*)sVt;
#pragma unroll
            for (int i = 0; i < 16; i++)
                vt[(seg * 16 + i) * (2 * AST) + row] = tmp[i];
        }
        __syncthreads();

        if (kt * 64 > wrow_min + 15) continue;

        // S = Q K^T (fp16), scale 1/8
        float s[8][4];
#pragma unroll
        for (int nb = 0; nb < 8; nb++) {
            s[nb][0] = s[nb][1] = s[nb][2] = s[nb][3] = 0.f;
#pragma unroll
            for (int c = 0; c < 4; c++) {
                const uint32_t* kr = sK + (nb * 8 + gr) * AST + 8 * c + tg;
                mma16h(s[nb], qa[c][0], qa[c][1], qa[c][2], qa[c][3], kr[0], kr[4]);
            }
#pragma unroll
            for (int e = 0; e < 4; e++) s[nb][e] *= INV_SCALE;
        }

        const int row0 = wrow_min + gr;
        const int row1 = row0 + 8;
        if (kt * 64 + 63 > wrow_min) {
#pragma unroll
            for (int nb = 0; nb < 8; nb++) {
                const int col = kt * 64 + nb * 8 + 2 * tg;
                if (col > row0)     s[nb][0] = -1e30f;
                if (col + 1 > row0) s[nb][1] = -1e30f;
                if (col > row1)     s[nb][2] = -1e30f;
                if (col + 1 > row1) s[nb][3] = -1e30f;
            }
        }

        // online softmax
        float lm0 = -1e30f, lm1 = -1e30f;
#pragma unroll
        for (int nb = 0; nb < 8; nb++) {
            lm0 = fmaxf(lm0, fmaxf(s[nb][0], s[nb][1]));
            lm1 = fmaxf(lm1, fmaxf(s[nb][2], s[nb][3]));
        }
        lm0 = fmaxf(lm0, __shfl_xor_sync(0xffffffffu, lm0, 1));
        lm0 = fmaxf(lm0, __shfl_xor_sync(0xffffffffu, lm0, 2));
        lm1 = fmaxf(lm1, __shfl_xor_sync(0xffffffffu, lm1, 1));
        lm1 = fmaxf(lm1, __shfl_xor_sync(0xffffffffu, lm1, 2));
        const float nm0 = fmaxf(m0, lm0), nm1 = fmaxf(m1, lm1);
        const float c0 = __expf(m0 - nm0), c1 = __expf(m1 - nm1);
        m0 = nm0; m1 = nm1;

        float ps0 = 0.f, ps1 = 0.f;
#pragma unroll
        for (int nb = 0; nb < 8; nb++) {
            s[nb][0] = __expf(s[nb][0] - m0);
            s[nb][1] = __expf(s[nb][1] - m0);
            s[nb][2] = __expf(s[nb][2] - m1);
            s[nb][3] = __expf(s[nb][3] - m1);
            ps0 += s[nb][0] + s[nb][1];
            ps1 += s[nb][2] + s[nb][3];
        }
        ps0 += __shfl_xor_sync(0xffffffffu, ps0, 1);
        ps0 += __shfl_xor_sync(0xffffffffu, ps0, 2);
        ps1 += __shfl_xor_sync(0xffffffffu, ps1, 1);
        ps1 += __shfl_xor_sync(0xffffffffu, ps1, 2);
        l0 = l0 * c0 + ps0;
        l1 = l1 * c1 + ps1;
#pragma unroll
        for (int nd = 0; nd < 8; nd++) {
            o[nd][0] *= c0; o[nd][1] *= c0;
            o[nd][2] *= c1; o[nd][3] *= c1;
        }

        // P -> fp16 register fragments
        uint32_t p01[8], p23[8];
#pragma unroll
        for (int nb = 0; nb < 8; nb++) {
            p01[nb] = h2u(__floats2half2_rn(s[nb][0], s[nb][1]));
            p23[nb] = h2u(__floats2half2_rn(s[nb][2], s[nb][3]));
        }

        // O += P V (B from transposed V tile)
#pragma unroll
        for (int c = 0; c < 4; c++) {
            const uint32_t a0 = p01[2 * c], a1 = p23[2 * c];
            const uint32_t a2 = p01[2 * c + 1], a3 = p23[2 * c + 1];
#pragma unroll
            for (int nd = 0; nd < 8; nd++) {
                const uint32_t* vr = sVt + (nd * 8 + gr) * AST + 8 * c + tg;
                mma16h(o[nd], a0, a1, a2, a3, vr[0], vr[4]);
            }
        }
    }

    // epilogue: normalize + half store
    const float il0 = 1.f / l0, il1 = 1.f / l1;
    const int grow0 = b * SS + qbase + w * 16 + gr;
    __half* d0 = outh + (size_t)grow0 * DD + h * DK;
    __half* d1 = d0 + 8 * DD;
#pragma unroll
    for (int nd = 0; nd < 8; nd++) {
        *(__half2*)(d0 + nd * 8 + 2 * tg) = __floats2half2_rn(o[nd][0] * il0, o[nd][1] * il0);
        *(__half2*)(d1 + nd * 8 + 2 * tg) = __floats2half2_rn(o[nd][2] * il1, o[nd][3] * il1);
    }
}

// ---------------- LayerNorm: warp-per-row, coalesced (lane-interleaved) -----
__global__ __launch_bounds__(256)
void ln_kernel(const float* __restrict__ in, const float* __restrict__ gamma,
               const float* __restrict__ beta, float* __restrict__ out,
               __half* __restrict__ outh)
{
    const int wid = threadIdx.x >> 5;
    const int lane = threadIdx.x & 31;
    const int row = blockIdx.x * 8 + wid;
    const float4* xr = (const float4*)(in + (size_t)row * DD);

    float4 v[4];
#pragma unroll
    for (int i = 0; i < 4; i++) v[i] = xr[lane + 32 * i];

    float s = 0.f, sq = 0.f;
#pragma unroll
    for (int i = 0; i < 4; i++) {
        s  += v[i].x + v[i].y + v[i].z + v[i].w;
        sq += v[i].x * v[i].x + v[i].y * v[i].y + v[i].z * v[i].z + v[i].w * v[i].w;
    }
#pragma unroll
    for (int off = 16; off > 0; off >>= 1) {
        s  += __shfl_xor_sync(0xffffffffu, s,  off);
        sq += __shfl_xor_sync(0xffffffffu, sq, off);
    }

    const float mean = s * (1.f / DD);
    const float var  = sq * (1.f / DD) - mean * mean;
    const float rstd = rsqrtf(var + EPS);

    const float4* gp = (const float4*)gamma;
    const float4* bp = (const float4*)beta;
    float4* op = (float4*)(out + (size_t)row * DD);
    __half2* hp = (__half2*)(outh + (size_t)row * DD);

#pragma unroll
    for (int i = 0; i < 4; i++) {
        const int idx = lane + 32 * i;
        const float4 gv = gp[idx];
        const float4 bv = bp[idx];
        float4 r;
        r.x = (v[i].x - mean) * rstd * gv.x + bv.x;
        r.y = (v[i].y - mean) * rstd * gv.y + bv.y;
        r.z = (v[i].z - mean) * rstd * gv.z + bv.z;
        r.w = (v[i].w - mean) * rstd * gv.w + bv.w;
        op[idx] = r;
        hp[2 * idx]     = __floats2half2_rn(r.x, r.y);
        hp[2 * idx + 1] = __floats2half2_rn(r.z, r.w);
    }
}

// ---------------- driver ----------------
extern "C" void kernel_launch(void* const* d_in, const int* in_sizes, int n_in,
                              void* d_out, int out_size)
{
    const float* x      = (const float*)d_in[0];
    const float* qkv_w  = (const float*)d_in[1];
    const float* qkv_b  = (const float*)d_in[2];
    const float* out_w  = (const float*)d_in[3];
    const float* out_b  = (const float*)d_in[4];
    const float* ln1_g  = (const float*)d_in[5];
    const float* ln1_b  = (const float*)d_in[6];
    const float* mlp_w1 = (const float*)d_in[7];
    const float* mlp_b1 = (const float*)d_in[8];
    const float* mlp_w2 = (const float*)d_in[9];
    const float* mlp_b2 = (const float*)d_in[10];
    const float* ln2_g  = (const float*)d_in[11];
    const float* ln2_b  = (const float*)d_in[12];
    float* outp = (float*)d_out;

    float *px, *pt2;
    __half *pxh, *pqkvh, *pattnh, *phh, *pqkvwt, *poutwt, *pw1t, *pw2t;
    cudaGetSymbolAddress((void**)&px,    g_x);
    cudaGetSymbolAddress((void**)&pxh,   g_xh);
    cudaGetSymbolAddress((void**)&pqkvh, g_qkvh);
    cudaGetSymbolAddress((void**)&pattnh,g_attnh);
    cudaGetSymbolAddress((void**)&phh,   g_hh);
    cudaGetSymbolAddress((void**)&pt2,   g_t2);
    cudaGetSymbolAddress((void**)&pqkvwt,g_qkv_wt);
    cudaGetSymbolAddress((void**)&poutwt,g_out_wt);
    cudaGetSymbolAddress((void**)&pw1t,  g_w1t);
    cudaGetSymbolAddress((void**)&pw2t,  g_w2t);

    cudaFuncSetAttribute(tc_gemm<false,false,true>, cudaFuncAttributeMaxDynamicSharedMemorySize, GSMEM_BYTES);
    cudaFuncSetAttribute(tc_gemm<false,true,false>, cudaFuncAttributeMaxDynamicSharedMemorySize, GSMEM_BYTES);
    cudaFuncSetAttribute(tc_gemm<true,false,true>,  cudaFuncAttributeMaxDynamicSharedMemorySize, GSMEM_BYTES);

    transpose_h<<<dim3(3*DD/32, DD/32, LL), dim3(32,8)>>>(qkv_w, pqkvwt, DD, 3*DD);
    transpose_h<<<dim3(DD/32,   DD/32, LL), dim3(32,8)>>>(out_w, poutwt, DD, DD);
    transpose_h<<<dim3(DFF/32,  DD/32, LL), dim3(32,8)>>>(mlp_w1, pw1t, DD, DFF);
    transpose_h<<<dim3(DD/32,  DFF/32, LL), dim3(32,8)>>>(mlp_w2, pw2t, DFF, DD);

    const int nX = MM * DD;
    copy_half_kernel<<<(nX/4 + 255)/256, 256>>>((const float4*)x, (float4*)px,
                                                (__half2*)pxh, nX/4);

    for (int i = 0; i < LL; i++) {
        // QKV: [8192,512] x [512,1536] (+bias) -> half
        tc_gemm<false,false,true><<<dim3(3*DD/BN, MM/BM), 256, GSMEM_BYTES>>>(
            pxh, pqkvwt + (size_t)i * 3*DD*DD, qkv_b + (size_t)i * 3*DD,
            nullptr, pqkvh, MM, 3*DD, DD);

        attn_h_kernel<<<dim3(SS/128, HH, BB), 256>>>(pqkvh, pattnh);

        // out-proj + residual(x) -> fp32 t2
        tc_gemm<false,true,false><<<dim3(DD/BN, MM/BM), 256, GSMEM_BYTES>>>(
            pattnh, poutwt + (size_t)i * DD*DD, out_b + (size_t)i * DD,
            px, pt2, MM, DD, DD);

        ln_kernel<<<MM/8, 256>>>(pt2, ln1_g + (size_t)i * DD, ln1_b + (size_t)i * DD, px, pxh);

        // MLP1 + ReLU -> half hh
        tc_gemm<true,false,true><<<dim3(DFF/BN, MM/BM), 256, GSMEM_BYTES>>>(
            pxh, pw1t + (size_t)i * DFF*DD, mlp_b1 + (size_t)i * DFF,
            nullptr, phh, MM, DFF, DD);

        // MLP2 + residual(x) -> fp32 t2
        tc_gemm<false,true,false><<<dim3(DD/BN, MM/BM), 256, GSMEM_BYTES>>>(
            phh, pw2t + (size_t)i * DD*DFF, mlp_b2 + (size_t)i * DD,
            px, pt2, MM, DD, DFF);

        float* lnout = (i == LL - 1) ? outp : px;
        ln_kernel<<<MM/8, 256>>>(pt2, ln2_g + (size_t)i * DD, ln2_b + (size_t)i * DD, lnout, pxh);
    }
}

// round 16
// speedup vs baseline: 1.6260x; 1.0821x over previous
#include <cuda_runtime.h>
#include <cuda_fp16.h>
#include <math.h>
#include <cstdint>

// Problem constants
#define BB 8
#define SS 1024
#define DD 512
#define HH 8
#define DK 64
#define DFF 2048
#define LL 6
#define MM (BB*SS)          // 8192 rows
#define EPS 1e-5f
#define INV_SCALE 0.125f

// fp16 GEMM tiling: 128x128 CTA tile, K-chunk 64 halves, 3-stage single-sync
#define BM 128
#define BN 128
#define BKC 64
#define ROW_U32 36                      // 32 data u32 + 4 pad (conflict-free)
#define TILE_U32 (128*ROW_U32)          // 4608
#define TILE_BYTES_H (TILE_U32*4)       // 18432
#define NSTAGE 3
#define GSMEM_BYTES (NSTAGE*2*TILE_BYTES_H)  // 110592

// fp16 attention smem strides (u32 units)
#define AST 36                          // 72 halves per row (64 data + 8 pad)

// ---------------- scratch ----------------
__device__ float  g_x[MM*DD];           // exact fp32 activations
__device__ __half g_xh[MM*DD];          // half copy (GEMM A operand)
__device__ __half g_qkvh[MM*3*DD];      // QKV in half
__device__ __half g_attnh[MM*DD];       // attention output (half)
__device__ __half g_hh[MM*DFF];         // MLP hidden (half)
__device__ float  g_t2[MM*DD];
// transposed half weights, [N,K] K-major
__device__ __half g_qkv_wt[LL*3*DD*DD];
__device__ __half g_out_wt[LL*DD*DD];
__device__ __half g_w1t[LL*DFF*DD];
__device__ __half g_w2t[LL*DD*DFF];

// ---------------- helpers ----------------
__device__ __forceinline__ uint32_t smem_u32(const void* p) {
    uint32_t a;
    asm("{ .reg .u64 t; cvta.to.shared.u64 t, %1; cvt.u32.u64 %0, t; }" : "=r"(a) : "l"(p));
    return a;
}
__device__ __forceinline__ void cp_async16(uint32_t dst, const void* src) {
    asm volatile("cp.async.cg.shared.global [%0], [%1], 16;" :: "r"(dst), "l"(src));
}
__device__ __forceinline__ void cp_commit() {
    asm volatile("cp.async.commit_group;" ::: "memory");
}
__device__ __forceinline__ void mma16h(float c[4], uint32_t a0, uint32_t a1,
                                       uint32_t a2, uint32_t a3,
                                       uint32_t b0, uint32_t b1) {
    asm volatile(
        "mma.sync.aligned.m16n8k16.row.col.f32.f16.f16.f32 "
        "{%0,%1,%2,%3}, {%4,%5,%6,%7}, {%8,%9}, {%0,%1,%2,%3};"
        : "+f"(c[0]), "+f"(c[1]), "+f"(c[2]), "+f"(c[3])
        : "r"(a0), "r"(a1), "r"(a2), "r"(a3), "r"(b0), "r"(b1));
}
__device__ __forceinline__ uint32_t h2u(__half2 h) { return *(uint32_t*)&h; }

// ---------------- elementwise ----------------
__global__ void copy_half_kernel(const float4* __restrict__ src, float4* __restrict__ dst,
                                 __half2* __restrict__ dsth, int n4) {
    int i = blockIdx.x * blockDim.x + threadIdx.x;
    if (i < n4) {
        float4 v = src[i];
        dst[i] = v;
        dsth[2*i]   = __floats2half2_rn(v.x, v.y);
        dsth[2*i+1] = __floats2half2_rn(v.z, v.w);
    }
}

// transpose + fp16 convert: W[L][K][N] -> Wt[L][N][K]
__global__ void transpose_h(const float* __restrict__ W, __half* __restrict__ Wt,
                            int K, int N) {
    __shared__ float t[32][33];
    const int l = blockIdx.z;
    const float* Wl = W + (size_t)l * K * N;
    __half* Wtl = Wt + (size_t)l * K * N;
    const int k0 = blockIdx.y * 32, n0 = blockIdx.x * 32;
    const int tx = threadIdx.x, ty = threadIdx.y;
#pragma unroll
    for (int i = 0; i < 32; i += 8)
        t[ty + i][tx] = Wl[(size_t)(k0 + ty + i) * N + n0 + tx];
    __syncthreads();
#pragma unroll
    for (int i = 0; i < 32; i += 8)
        Wtl[(size_t)(n0 + ty + i) * K + k0 + tx] = __float2half(t[tx][ty + i]);
}

// ---------------- fp16 mma GEMM: C[M,N] = A[M,K] @ Wt[N,K]^T ----------
// 3-stage ring, single __syncthreads per chunk, K-chunk = 64 halves.
template<bool RELU, bool RESID, bool HOUT>
__global__ __launch_bounds__(256)
void tc_gemm(const __half* __restrict__ A, const __half* __restrict__ Bw,
             const float* __restrict__ bias, const float* __restrict__ resid,
             void* __restrict__ Cv, int M, int N, int K)
{
    extern __shared__ float smemf[];
    const uint32_t sb = smem_u32(smemf);

    const int tid = threadIdx.x;
    const int wid = tid >> 5;
    const int lane = tid & 31;
    const int bx = blockIdx.x, by = blockIdx.y;

    const __half* Ag = A + (size_t)by * BM * K;
    const __half* Bg = Bw + (size_t)bx * BN * K;

    auto issue_chunk = [&](int chunk, int buf) {
        const int k0 = chunk * BKC;
        const uint32_t base = sb + (uint32_t)buf * (2u * TILE_BYTES_H);
#pragma unroll
        for (int p = 0; p < 4; p++) {
            const int idx = p * 256 + tid;      // 0..1023
            const int row = idx >> 3;
            const int j = idx & 7;
            cp_async16(base + (uint32_t)row * (ROW_U32*4) + (uint32_t)j * 16,
                       Ag + (size_t)row * K + k0 + j * 8);
        }
#pragma unroll
        for (int p = 0; p < 4; p++) {
            const int idx = p * 256 + tid;
            const int row = idx >> 3;
            const int j = idx & 7;
            cp_async16(base + TILE_BYTES_H + (uint32_t)row * (ROW_U32*4) + (uint32_t)j * 16,
                       Bg + (size_t)row * K + k0 + j * 8);
        }
        cp_commit();
    };

    const int nc = K / BKC;        // 8 or 32 (always >= 3)
    issue_chunk(0, 0);
    issue_chunk(1, 1);

    const int wm = (wid >> 2) * 64;
    const int wn = (wid & 3) * 32;
    const int qr = lane >> 2;
    const int qc = lane & 3;

    float acc[4][4][4];
#pragma unroll
    for (int mi = 0; mi < 4; mi++)
#pragma unroll
        for (int ni = 0; ni < 4; ni++)
#pragma unroll
            for (int e = 0; e < 4; e++) acc[mi][ni][e] = 0.f;

    int buf = 0;      // buffer holding chunk c
    int nbuf = 2;     // buffer for chunk c+2
    for (int c = 0; c < nc; c++) {
        if (c + 1 < nc) asm volatile("cp.async.wait_group 1;" ::: "memory");
        else            asm volatile("cp.async.wait_group 0;" ::: "memory");
        __syncthreads();
        // safe: buffer nbuf == (c+2)%3 == (c-1)%3 whose readers all passed the sync
        if (c + 2 < nc) issue_chunk(c + 2, nbuf);

        const uint32_t* sAu = reinterpret_cast<const uint32_t*>(smemf) + buf * (2 * TILE_U32);
        const uint32_t* sBu = sAu + TILE_U32;

#pragma unroll
        for (int ks = 0; ks < 4; ks++) {
            const int col = ks * 8 + qc;
            uint32_t bfr[4][2];
#pragma unroll
            for (int ni = 0; ni < 4; ni++) {
                const int n = wn + ni * 8 + qr;
                bfr[ni][0] = sBu[n * ROW_U32 + col];
                bfr[ni][1] = sBu[n * ROW_U32 + col + 4];
            }
#pragma unroll
            for (int mi = 0; mi < 4; mi++) {
                const int r = wm + mi * 16 + qr;
                const uint32_t a0 = sAu[r * ROW_U32 + col];
                const uint32_t a1 = sAu[(r + 8) * ROW_U32 + col];
                const uint32_t a2 = sAu[r * ROW_U32 + col + 4];
                const uint32_t a3 = sAu[(r + 8) * ROW_U32 + col + 4];
#pragma unroll
                for (int ni = 0; ni < 4; ni++)
                    mma16h(acc[mi][ni], a0, a1, a2, a3, bfr[ni][0], bfr[ni][1]);
            }
        }
        buf  = (buf  == NSTAGE - 1) ? 0 : buf + 1;
        nbuf = (nbuf == NSTAGE - 1) ? 0 : nbuf + 1;
    }

#pragma unroll
    for (int mi = 0; mi < 4; mi++) {
#pragma unroll
        for (int ni = 0; ni < 4; ni++) {
            const int r0 = by * BM + wm + mi * 16 + qr;
            const int c0 = bx * BN + wn + ni * 8 + qc * 2;
            const float2 bv = *(const float2*)(bias + c0);
#pragma unroll
            for (int hrow = 0; hrow < 2; hrow++) {
                const int rr = r0 + hrow * 8;
                float v0 = acc[mi][ni][hrow * 2 + 0] + bv.x;
                float v1 = acc[mi][ni][hrow * 2 + 1] + bv.y;
                if (RESID) {
                    const float2 rv = *(const float2*)(resid + (size_t)rr * N + c0);
                    v0 += rv.x; v1 += rv.y;
                }
                if (RELU) { v0 = fmaxf(v0, 0.f); v1 = fmaxf(v1, 0.f); }
                if (HOUT) {
                    *(__half2*)((__half*)Cv + (size_t)rr * N + c0) = __floats2half2_rn(v0, v1);
                } else {
                    *(float2*)((float*)Cv + (size_t)rr * N + c0) = make_float2(v0, v1);
                }
            }
        }
    }
}

// ---------------- flash attention, full fp16 mma (round-9 proven form) ------
__global__ __launch_bounds__(256, 1)
void attn_h_kernel(const __half* __restrict__ qkvh, __half* __restrict__ outh)
{
    __shared__ uint32_t sQ[128*AST];    // 18432 B
    __shared__ uint32_t sK[64*AST];     //  9216 B
    __shared__ uint32_t sVt[64*AST];    //  9216 B (V transposed: [d][key])

    const int qblk = blockIdx.x;
    const int h = blockIdx.y;
    const int b = blockIdx.z;
    const int tid = threadIdx.x;
    const int w = tid >> 5;
    const int lane = tid & 31;
    const int gr = lane >> 2;
    const int tg = lane & 3;
    const int qbase = qblk * 128;

    // stage Q tile (half, row-major [128][64])
    {
        const int row = tid >> 1, seg = tid & 1;
        const __half* src = qkvh + ((size_t)(b * SS + qbase + row)) * (3 * DD) + h * DK + seg * 32;
        uint4* dst = (uint4*)(sQ + row * AST + seg * 16);
        const uint4* s4 = (const uint4*)src;
#pragma unroll
        for (int i = 0; i < 4; i++) dst[i] = s4[i];
    }
    __syncthreads();

    // Q A-fragments: 4 k-chunks of 16 halves
    uint32_t qa[4][4];
    {
        const uint32_t* qw = sQ + (w * 16) * AST;
#pragma unroll
        for (int c = 0; c < 4; c++) {
            qa[c][0] = qw[gr * AST + 8 * c + tg];
            qa[c][1] = qw[(gr + 8) * AST + 8 * c + tg];
            qa[c][2] = qw[gr * AST + 8 * c + tg + 4];
            qa[c][3] = qw[(gr + 8) * AST + 8 * c + tg + 4];
        }
    }

    float o[8][4];
#pragma unroll
    for (int nd = 0; nd < 8; nd++)
#pragma unroll
        for (int e = 0; e < 4; e++) o[nd][e] = 0.f;
    float m0 = -1e30f, m1 = -1e30f, l0 = 0.f, l1 = 0.f;

    const int ntiles = 2 * qblk + 2;
    const int wrow_min = qbase + w * 16;

    for (int kt = 0; kt < ntiles; kt++) {
        __syncthreads();
        // load K tile [64 keys][64 dims] and V transposed [64 dims][64 keys]
        {
            const int row = tid >> 2, seg = tid & 3;
            const __half* kb = qkvh + ((size_t)(b * SS + kt * 64 + row)) * (3 * DD)
                             + DD + h * DK + seg * 16;
            uint4* dk = (uint4*)(sK + row * AST + seg * 8);
            dk[0] = ((const uint4*)kb)[0];
            dk[1] = ((const uint4*)kb)[1];

            const __half* vb = kb + DD;
            __half tmp[16];
            *(uint4*)tmp       = ((const uint4*)vb)[0];
            *(uint4*)(tmp + 8) = ((const uint4*)vb)[1];
            __half* vt = (__half*)sVt;
#pragma unroll
            for (int i = 0; i < 16; i++)
                vt[(seg * 16 + i) * (2 * AST) + row] = tmp[i];
        }
        __syncthreads();

        if (kt * 64 > wrow_min + 15) continue;

        // S = Q K^T (fp16), scale 1/8
        float s[8][4];
#pragma unroll
        for (int nb = 0; nb < 8; nb++) {
            s[nb][0] = s[nb][1] = s[nb][2] = s[nb][3] = 0.f;
#pragma unroll
            for (int c = 0; c < 4; c++) {
                const uint32_t* kr = sK + (nb * 8 + gr) * AST + 8 * c + tg;
                mma16h(s[nb], qa[c][0], qa[c][1], qa[c][2], qa[c][3], kr[0], kr[4]);
            }
#pragma unroll
            for (int e = 0; e < 4; e++) s[nb][e] *= INV_SCALE;
        }

        const int row0 = wrow_min + gr;
        const int row1 = row0 + 8;
        if (kt * 64 + 63 > wrow_min) {
#pragma unroll
            for (int nb = 0; nb < 8; nb++) {
                const int col = kt * 64 + nb * 8 + 2 * tg;
                if (col > row0)     s[nb][0] = -1e30f;
                if (col + 1 > row0) s[nb][1] = -1e30f;
                if (col > row1)     s[nb][2] = -1e30f;
                if (col + 1 > row1) s[nb][3] = -1e30f;
            }
        }

        // online softmax
        float lm0 = -1e30f, lm1 = -1e30f;
#pragma unroll
        for (int nb = 0; nb < 8; nb++) {
            lm0 = fmaxf(lm0, fmaxf(s[nb][0], s[nb][1]));
            lm1 = fmaxf(lm1, fmaxf(s[nb][2], s[nb][3]));
        }
        lm0 = fmaxf(lm0, __shfl_xor_sync(0xffffffffu, lm0, 1));
        lm0 = fmaxf(lm0, __shfl_xor_sync(0xffffffffu, lm0, 2));
        lm1 = fmaxf(lm1, __shfl_xor_sync(0xffffffffu, lm1, 1));
        lm1 = fmaxf(lm1, __shfl_xor_sync(0xffffffffu, lm1, 2));
        const float nm0 = fmaxf(m0, lm0), nm1 = fmaxf(m1, lm1);
        const float c0 = __expf(m0 - nm0), c1 = __expf(m1 - nm1);
        m0 = nm0; m1 = nm1;

        float ps0 = 0.f, ps1 = 0.f;
#pragma unroll
        for (int nb = 0; nb < 8; nb++) {
            s[nb][0] = __expf(s[nb][0] - m0);
            s[nb][1] = __expf(s[nb][1] - m0);
            s[nb][2] = __expf(s[nb][2] - m1);
            s[nb][3] = __expf(s[nb][3] - m1);
            ps0 += s[nb][0] + s[nb][1];
            ps1 += s[nb][2] + s[nb][3];
        }
        ps0 += __shfl_xor_sync(0xffffffffu, ps0, 1);
        ps0 += __shfl_xor_sync(0xffffffffu, ps0, 2);
        ps1 += __shfl_xor_sync(0xffffffffu, ps1, 1);
        ps1 += __shfl_xor_sync(0xffffffffu, ps1, 2);
        l0 = l0 * c0 + ps0;
        l1 = l1 * c1 + ps1;
#pragma unroll
        for (int nd = 0; nd < 8; nd++) {
            o[nd][0] *= c0; o[nd][1] *= c0;
            o[nd][2] *= c1; o[nd][3] *= c1;
        }

        // P -> fp16 register fragments
        uint32_t p01[8], p23[8];
#pragma unroll
        for (int nb = 0; nb < 8; nb++) {
            p01[nb] = h2u(__floats2half2_rn(s[nb][0], s[nb][1]));
            p23[nb] = h2u(__floats2half2_rn(s[nb][2], s[nb][3]));
        }

        // O += P V (B from transposed V tile)
#pragma unroll
        for (int c = 0; c < 4; c++) {
            const uint32_t a0 = p01[2 * c], a1 = p23[2 * c];
            const uint32_t a2 = p01[2 * c + 1], a3 = p23[2 * c + 1];
#pragma unroll
            for (int nd = 0; nd < 8; nd++) {
                const uint32_t* vr = sVt + (nd * 8 + gr) * AST + 8 * c + tg;
                mma16h(o[nd], a0, a1, a2, a3, vr[0], vr[4]);
            }
        }
    }

    // epilogue: normalize + half store
    const float il0 = 1.f / l0, il1 = 1.f / l1;
    const int grow0 = b * SS + qbase + w * 16 + gr;
    __half* d0 = outh + (size_t)grow0 * DD + h * DK;
    __half* d1 = d0 + 8 * DD;
#pragma unroll
    for (int nd = 0; nd < 8; nd++) {
        *(__half2*)(d0 + nd * 8 + 2 * tg) = __floats2half2_rn(o[nd][0] * il0, o[nd][1] * il0);
        *(__half2*)(d1 + nd * 8 + 2 * tg) = __floats2half2_rn(o[nd][2] * il1, o[nd][3] * il1);
    }
}

// ---------------- LayerNorm: warp-per-row, coalesced (lane-interleaved) -----
__global__ __launch_bounds__(256)
void ln_kernel(const float* __restrict__ in, const float* __restrict__ gamma,
               const float* __restrict__ beta, float* __restrict__ out,
               __half* __restrict__ outh)
{
    const int wid = threadIdx.x >> 5;
    const int lane = threadIdx.x & 31;
    const int row = blockIdx.x * 8 + wid;
    const float4* xr = (const float4*)(in + (size_t)row * DD);

    float4 v[4];
#pragma unroll
    for (int i = 0; i < 4; i++) v[i] = xr[lane + 32 * i];

    float s = 0.f, sq = 0.f;
#pragma unroll
    for (int i = 0; i < 4; i++) {
        s  += v[i].x + v[i].y + v[i].z + v[i].w;
        sq += v[i].x * v[i].x + v[i].y * v[i].y + v[i].z * v[i].z + v[i].w * v[i].w;
    }
#pragma unroll
    for (int off = 16; off > 0; off >>= 1) {
        s  += __shfl_xor_sync(0xffffffffu, s,  off);
        sq += __shfl_xor_sync(0xffffffffu, sq, off);
    }

    const float mean = s * (1.f / DD);
    const float var  = sq * (1.f / DD) - mean * mean;
    const float rstd = rsqrtf(var + EPS);

    const float4* gp = (const float4*)gamma;
    const float4* bp = (const float4*)beta;
    float4* op = (float4*)(out + (size_t)row * DD);
    __half2* hp = (__half2*)(outh + (size_t)row * DD);

#pragma unroll
    for (int i = 0; i < 4; i++) {
        const int idx = lane + 32 * i;
        const float4 gv = gp[idx];
        const float4 bv = bp[idx];
        float4 r;
        r.x = (v[i].x - mean) * rstd * gv.x + bv.x;
        r.y = (v[i].y - mean) * rstd * gv.y + bv.y;
        r.z = (v[i].z - mean) * rstd * gv.z + bv.z;
        r.w = (v[i].w - mean) * rstd * gv.w + bv.w;
        op[idx] = r;
        hp[2 * idx]     = __floats2half2_rn(r.x, r.y);
        hp[2 * idx + 1] = __floats2half2_rn(r.z, r.w);
    }
}

// ---------------- driver ----------------
extern "C" void kernel_launch(void* const* d_in, const int* in_sizes, int n_in,
                              void* d_out, int out_size)
{
    const float* x      = (const float*)d_in[0];
    const float* qkv_w  = (const float*)d_in[1];
    const float* qkv_b  = (const float*)d_in[2];
    const float* out_w  = (const float*)d_in[3];
    const float* out_b  = (const float*)d_in[4];
    const float* ln1_g  = (const float*)d_in[5];
    const float* ln1_b  = (const float*)d_in[6];
    const float* mlp_w1 = (const float*)d_in[7];
    const float* mlp_b1 = (const float*)d_in[8];
    const float* mlp_w2 = (const float*)d_in[9];
    const float* mlp_b2 = (const float*)d_in[10];
    const float* ln2_g  = (const float*)d_in[11];
    const float* ln2_b  = (const float*)d_in[12];
    float* outp = (float*)d_out;

    float *px, *pt2;
    __half *pxh, *pqkvh, *pattnh, *phh, *pqkvwt, *poutwt, *pw1t, *pw2t;
    cudaGetSymbolAddress((void**)&px,    g_x);
    cudaGetSymbolAddress((void**)&pxh,   g_xh);
    cudaGetSymbolAddress((void**)&pqkvh, g_qkvh);
    cudaGetSymbolAddress((void**)&pattnh,g_attnh);
    cudaGetSymbolAddress((void**)&phh,   g_hh);
    cudaGetSymbolAddress((void**)&pt2,   g_t2);
    cudaGetSymbolAddress((void**)&pqkvwt,g_qkv_wt);
    cudaGetSymbolAddress((void**)&poutwt,g_out_wt);
    cudaGetSymbolAddress((void**)&pw1t,  g_w1t);
    cudaGetSymbolAddress((void**)&pw2t,  g_w2t);

    cudaFuncSetAttribute(tc_gemm<false,false,true>, cudaFuncAttributeMaxDynamicSharedMemorySize, GSMEM_BYTES);
    cudaFuncSetAttribute(tc_gemm<false,true,false>, cudaFuncAttributeMaxDynamicSharedMemorySize, GSMEM_BYTES);
    cudaFuncSetAttribute(tc_gemm<true,false,true>,  cudaFuncAttributeMaxDynamicSharedMemorySize, GSMEM_BYTES);

    transpose_h<<<dim3(3*DD/32, DD/32, LL), dim3(32,8)>>>(qkv_w, pqkvwt, DD, 3*DD);
    transpose_h<<<dim3(DD/32,   DD/32, LL), dim3(32,8)>>>(out_w, poutwt, DD, DD);
    transpose_h<<<dim3(DFF/32,  DD/32, LL), dim3(32,8)>>>(mlp_w1, pw1t, DD, DFF);
    transpose_h<<<dim3(DD/32,  DFF/32, LL), dim3(32,8)>>>(mlp_w2, pw2t, DFF, DD);

    const int nX = MM * DD;
    copy_half_kernel<<<(nX/4 + 255)/256, 256>>>((const float4*)x, (float4*)px,
                                                (__half2*)pxh, nX/4);

    for (int i = 0; i < LL; i++) {
        // QKV: [8192,512] x [512,1536] (+bias) -> half
        tc_gemm<false,false,true><<<dim3(3*DD/BN, MM/BM), 256, GSMEM_BYTES>>>(
            pxh, pqkvwt + (size_t)i * 3*DD*DD, qkv_b + (size_t)i * 3*DD,
            nullptr, pqkvh, MM, 3*DD, DD);

        attn_h_kernel<<<dim3(SS/128, HH, BB), 256>>>(pqkvh, pattnh);

        // out-proj + residual(x) -> fp32 t2
        tc_gemm<false,true,false><<<dim3(DD/BN, MM/BM), 256, GSMEM_BYTES>>>(
            pattnh, poutwt + (size_t)i * DD*DD, out_b + (size_t)i * DD,
            px, pt2, MM, DD, DD);

        ln_kernel<<<MM/8, 256>>>(pt2, ln1_g + (size_t)i * DD, ln1_b + (size_t)i * DD, px, pxh);

        // MLP1 + ReLU -> half hh
        tc_gemm<true,false,true><<<dim3(DFF/BN, MM/BM), 256, GSMEM_BYTES>>>(
            pxh, pw1t + (size_t)i * DFF*DD, mlp_b1 + (size_t)i * DFF,
            nullptr, phh, MM, DFF, DD);

        // MLP2 + residual(x) -> fp32 t2
        tc_gemm<false,true,false><<<dim3(DD/BN, MM/BM), 256, GSMEM_BYTES>>>(
            phh, pw2t + (size_t)i * DD*DFF, mlp_b2 + (size_t)i * DD,
            px, pt2, MM, DD, DFF);

        float* lnout = (i == LL - 1) ? outp : px;
        ln_kernel<<<MM/8, 256>>>(pt2, ln2_g + (size_t)i * DD, ln2_b + (size_t)i * DD, lnout, pxh);
    }
}

// round 17
// speedup vs baseline: 1.6512x; 1.0155x over previous
#include <cuda_runtime.h>
#include <cuda_fp16.h>
#include <math.h>
#include <cstdint>

// Problem constants
#define BB 8
#define SS 1024
#define DD 512
#define HH 8
#define DK 64
#define DFF 2048
#define LL 6
#define MM (BB*SS)          // 8192 rows
#define EPS 1e-5f
#define INV_SCALE 0.125f

// fp16 GEMM tiling: 128x128 CTA tile, K-chunk 64 halves, 3-stage single-sync
#define BM 128
#define BN 128
#define BKC 64
#define ROW_U32 36                      // 32 data u32 + 4 pad (conflict-free)
#define TILE_U32 (128*ROW_U32)          // 4608
#define TILE_BYTES_H (TILE_U32*4)       // 18432
#define NSTAGE 3
#define GSMEM_BYTES (NSTAGE*2*TILE_BYTES_H)  // 110592

// fp16 attention smem strides (u32 units)
#define AST 36                          // 72 halves per row (64 data + 8 pad)

// ---------------- scratch ----------------
__device__ float  g_x[MM*DD];           // exact fp32 activations (residual stream)
__device__ __half g_xh[MM*DD];          // half copy (GEMM A operand)
__device__ __half g_qkvh[MM*3*DD];      // QKV in half
__device__ __half g_attnh[MM*DD];       // attention output (half)
__device__ __half g_hh[MM*DFF];         // MLP hidden (half)
__device__ __half g_t2h[MM*DD];         // raw GEMM output (pre-residual, half)
// transposed half weights, [N,K] K-major
__device__ __half g_qkv_wt[LL*3*DD*DD];
__device__ __half g_out_wt[LL*DD*DD];
__device__ __half g_w1t[LL*DFF*DD];
__device__ __half g_w2t[LL*DD*DFF];

// ---------------- helpers ----------------
__device__ __forceinline__ uint32_t smem_u32(const void* p) {
    uint32_t a;
    asm("{ .reg .u64 t; cvta.to.shared.u64 t, %1; cvt.u32.u64 %0, t; }" : "=r"(a) : "l"(p));
    return a;
}
__device__ __forceinline__ void cp_async16(uint32_t dst, const void* src) {
    asm volatile("cp.async.cg.shared.global [%0], [%1], 16;" :: "r"(dst), "l"(src));
}
__device__ __forceinline__ void cp_commit() {
    asm volatile("cp.async.commit_group;" ::: "memory");
}
__device__ __forceinline__ void mma16h(float c[4], uint32_t a0, uint32_t a1,
                                       uint32_t a2, uint32_t a3,
                                       uint32_t b0, uint32_t b1) {
    asm volatile(
        "mma.sync.aligned.m16n8k16.row.col.f32.f16.f16.f32 "
        "{%0,%1,%2,%3}, {%4,%5,%6,%7}, {%8,%9}, {%0,%1,%2,%3};"
        : "+f"(c[0]), "+f"(c[1]), "+f"(c[2]), "+f"(c[3])
        : "r"(a0), "r"(a1), "r"(a2), "r"(a3), "r"(b0), "r"(b1));
}
__device__ __forceinline__ uint32_t h2u(__half2 h) { return *(uint32_t*)&h; }

// ---------------- elementwise ----------------
__global__ void copy_half_kernel(const float4* __restrict__ src, float4* __restrict__ dst,
                                 __half2* __restrict__ dsth, int n4) {
    int i = blockIdx.x * blockDim.x + threadIdx.x;
    if (i < n4) {
        float4 v = src[i];
        dst[i] = v;
        dsth[2*i]   = __floats2half2_rn(v.x, v.y);
        dsth[2*i+1] = __floats2half2_rn(v.z, v.w);
    }
}

// transpose + fp16 convert: W[L][K][N] -> Wt[L][N][K]
__global__ void transpose_h(const float* __restrict__ W, __half* __restrict__ Wt,
                            int K, int N) {
    __shared__ float t[32][33];
    const int l = blockIdx.z;
    const float* Wl = W + (size_t)l * K * N;
    __half* Wtl = Wt + (size_t)l * K * N;
    const int k0 = blockIdx.y * 32, n0 = blockIdx.x * 32;
    const int tx = threadIdx.x, ty = threadIdx.y;
#pragma unroll
    for (int i = 0; i < 32; i += 8)
        t[ty + i][tx] = Wl[(size_t)(k0 + ty + i) * N + n0 + tx];
    __syncthreads();
#pragma unroll
    for (int i = 0; i < 32; i += 8)
        Wtl[(size_t)(n0 + ty + i) * K + k0 + tx] = __float2half(t[tx][ty + i]);
}

// ---------------- fp16 mma GEMM: C[M,N] = A[M,K] @ Wt[N,K]^T ----------
// 3-stage ring, single __syncthreads per chunk, K-chunk = 64 halves.
template<bool RELU, bool HOUT>
__global__ __launch_bounds__(256)
void tc_gemm(const __half* __restrict__ A, const __half* __restrict__ Bw,
             const float* __restrict__ bias,
             void* __restrict__ Cv, int M, int N, int K)
{
    extern __shared__ float smemf[];
    const uint32_t sb = smem_u32(smemf);

    const int tid = threadIdx.x;
    const int wid = tid >> 5;
    const int lane = tid & 31;
    const int bx = blockIdx.x, by = blockIdx.y;

    const __half* Ag = A + (size_t)by * BM * K;
    const __half* Bg = Bw + (size_t)bx * BN * K;

    auto issue_chunk = [&](int chunk, int buf) {
        const int k0 = chunk * BKC;
        const uint32_t base = sb + (uint32_t)buf * (2u * TILE_BYTES_H);
#pragma unroll
        for (int p = 0; p < 4; p++) {
            const int idx = p * 256 + tid;      // 0..1023
            const int row = idx >> 3;
            const int j = idx & 7;
            cp_async16(base + (uint32_t)row * (ROW_U32*4) + (uint32_t)j * 16,
                       Ag + (size_t)row * K + k0 + j * 8);
        }
#pragma unroll
        for (int p = 0; p < 4; p++) {
            const int idx = p * 256 + tid;
            const int row = idx >> 3;
            const int j = idx & 7;
            cp_async16(base + TILE_BYTES_H + (uint32_t)row * (ROW_U32*4) + (uint32_t)j * 16,
                       Bg + (size_t)row * K + k0 + j * 8);
        }
        cp_commit();
    };

    const int nc = K / BKC;        // 8 or 32 (always >= 3)
    issue_chunk(0, 0);
    issue_chunk(1, 1);

    const int wm = (wid >> 2) * 64;
    const int wn = (wid & 3) * 32;
    const int qr = lane >> 2;
    const int qc = lane & 3;

    float acc[4][4][4];
#pragma unroll
    for (int mi = 0; mi < 4; mi++)
#pragma unroll
        for (int ni = 0; ni < 4; ni++)
#pragma unroll
            for (int e = 0; e < 4; e++) acc[mi][ni][e] = 0.f;

    int buf = 0;      // buffer holding chunk c
    int nbuf = 2;     // buffer for chunk c+2
    for (int c = 0; c < nc; c++) {
        if (c + 1 < nc) asm volatile("cp.async.wait_group 1;" ::: "memory");
        else            asm volatile("cp.async.wait_group 0;" ::: "memory");
        __syncthreads();
        if (c + 2 < nc) issue_chunk(c + 2, nbuf);

        const uint32_t* sAu = reinterpret_cast<const uint32_t*>(smemf) + buf * (2 * TILE_U32);
        const uint32_t* sBu = sAu + TILE_U32;

#pragma unroll
        for (int ks = 0; ks < 4; ks++) {
            const int col = ks * 8 + qc;
            uint32_t bfr[4][2];
#pragma unroll
            for (int ni = 0; ni < 4; ni++) {
                const int n = wn + ni * 8 + qr;
                bfr[ni][0] = sBu[n * ROW_U32 + col];
                bfr[ni][1] = sBu[n * ROW_U32 + col + 4];
            }
#pragma unroll
            for (int mi = 0; mi < 4; mi++) {
                const int r = wm + mi * 16 + qr;
                const uint32_t a0 = sAu[r * ROW_U32 + col];
                const uint32_t a1 = sAu[(r + 8) * ROW_U32 + col];
                const uint32_t a2 = sAu[r * ROW_U32 + col + 4];
                const uint32_t a3 = sAu[(r + 8) * ROW_U32 + col + 4];
#pragma unroll
                for (int ni = 0; ni < 4; ni++)
                    mma16h(acc[mi][ni], a0, a1, a2, a3, bfr[ni][0], bfr[ni][1]);
            }
        }
        buf  = (buf  == NSTAGE - 1) ? 0 : buf + 1;
        nbuf = (nbuf == NSTAGE - 1) ? 0 : nbuf + 1;
    }

#pragma unroll
    for (int mi = 0; mi < 4; mi++) {
#pragma unroll
        for (int ni = 0; ni < 4; ni++) {
            const int r0 = by * BM + wm + mi * 16 + qr;
            const int c0 = bx * BN + wn + ni * 8 + qc * 2;
            const float2 bv = *(const float2*)(bias + c0);
#pragma unroll
            for (int hrow = 0; hrow < 2; hrow++) {
                const int rr = r0 + hrow * 8;
                float v0 = acc[mi][ni][hrow * 2 + 0] + bv.x;
                float v1 = acc[mi][ni][hrow * 2 + 1] + bv.y;
                if (RELU) { v0 = fmaxf(v0, 0.f); v1 = fmaxf(v1, 0.f); }
                if (HOUT) {
                    *(__half2*)((__half*)Cv + (size_t)rr * N + c0) = __floats2half2_rn(v0, v1);
                } else {
                    *(float2*)((float*)Cv + (size_t)rr * N + c0) = make_float2(v0, v1);
                }
            }
        }
    }
}

// ---------------- flash attention, full fp16 mma (round-9 proven form) ------
__global__ __launch_bounds__(256, 1)
void attn_h_kernel(const __half* __restrict__ qkvh, __half* __restrict__ outh)
{
    __shared__ uint32_t sQ[128*AST];    // 18432 B
    __shared__ uint32_t sK[64*AST];     //  9216 B
    __shared__ uint32_t sVt[64*AST];    //  9216 B (V transposed: [d][key])

    const int qblk = blockIdx.x;
    const int h = blockIdx.y;
    const int b = blockIdx.z;
    const int tid = threadIdx.x;
    const int w = tid >> 5;
    const int lane = tid & 31;
    const int gr = lane >> 2;
    const int tg = lane & 3;
    const int qbase = qblk * 128;

    // stage Q tile (half, row-major [128][64])
    {
        const int row = tid >> 1, seg = tid & 1;
        const __half* src = qkvh + ((size_t)(b * SS + qbase + row)) * (3 * DD) + h * DK + seg * 32;
        uint4* dst = (uint4*)(sQ + row * AST + seg * 16);
        const uint4* s4 = (const uint4*)src;
#pragma unroll
        for (int i = 0; i < 4; i++) dst[i] = s4[i];
    }
    __syncthreads();

    // Q A-fragments: 4 k-chunks of 16 halves
    uint32_t qa[4][4];
    {
        const uint32_t* qw = sQ + (w * 16) * AST;
#pragma unroll
        for (int c = 0; c < 4; c++) {
            qa[c][0] = qw[gr * AST + 8 * c + tg];
            qa[c][1] = qw[(gr + 8) * AST + 8 * c + tg];
            qa[c][2] = qw[gr * AST + 8 * c + tg + 4];
            qa[c][3] = qw[(gr + 8) * AST + 8 * c + tg + 4];
        }
    }

    float o[8][4];
#pragma unroll
    for (int nd = 0; nd < 8; nd++)
#pragma unroll
        for (int e = 0; e < 4; e++) o[nd][e] = 0.f;
    float m0 = -1e30f, m1 = -1e30f, l0 = 0.f, l1 = 0.f;

    const int ntiles = 2 * qblk + 2;
    const int wrow_min = qbase + w * 16;

    for (int kt = 0; kt < ntiles; kt++) {
        __syncthreads();
        // load K tile [64 keys][64 dims] and V transposed [64 dims][64 keys]
        {
            const int row = tid >> 2, seg = tid & 3;
            const __half* kb = qkvh + ((size_t)(b * SS + kt * 64 + row)) * (3 * DD)
                             + DD + h * DK + seg * 16;
            uint4* dk = (uint4*)(sK + row * AST + seg * 8);
            dk[0] = ((const uint4*)kb)[0];
            dk[1] = ((const uint4*)kb)[1];

            const __half* vb = kb + DD;
            __half tmp[16];
            *(uint4*)tmp       = ((const uint4*)vb)[0];
            *(uint4*)(tmp + 8) = ((const uint4*)vb)[1];
            __half* vt = (__half*)sVt;
#pragma unroll
            for (int i = 0; i < 16; i++)
                vt[(seg * 16 + i) * (2 * AST) + row] = tmp[i];
        }
        __syncthreads();

        if (kt * 64 > wrow_min + 15) continue;

        // S = Q K^T (fp16), scale 1/8
        float s[8][4];
#pragma unroll
        for (int nb = 0; nb < 8; nb++) {
            s[nb][0] = s[nb][1] = s[nb][2] = s[nb][3] = 0.f;
#pragma unroll
            for (int c = 0; c < 4; c++) {
                const uint32_t* kr = sK + (nb * 8 + gr) * AST + 8 * c + tg;
                mma16h(s[nb], qa[c][0], qa[c][1], qa[c][2], qa[c][3], kr[0], kr[4]);
            }
#pragma unroll
            for (int e = 0; e < 4; e++) s[nb][e] *= INV_SCALE;
        }

        const int row0 = wrow_min + gr;
        const int row1 = row0 + 8;
        if (kt * 64 + 63 > wrow_min) {
#pragma unroll
            for (int nb = 0; nb < 8; nb++) {
                const int col = kt * 64 + nb * 8 + 2 * tg;
                if (col > row0)     s[nb][0] = -1e30f;
                if (col + 1 > row0) s[nb][1] = -1e30f;
                if (col > row1)     s[nb][2] = -1e30f;
                if (col + 1 > row1) s[nb][3] = -1e30f;
            }
        }

        // online softmax
        float lm0 = -1e30f, lm1 = -1e30f;
#pragma unroll
        for (int nb = 0; nb < 8; nb++) {
            lm0 = fmaxf(lm0, fmaxf(s[nb][0], s[nb][1]));
            lm1 = fmaxf(lm1, fmaxf(s[nb][2], s[nb][3]));
        }
        lm0 = fmaxf(lm0, __shfl_xor_sync(0xffffffffu, lm0, 1));
        lm0 = fmaxf(lm0, __shfl_xor_sync(0xffffffffu, lm0, 2));
        lm1 = fmaxf(lm1, __shfl_xor_sync(0xffffffffu, lm1, 1));
        lm1 = fmaxf(lm1, __shfl_xor_sync(0xffffffffu, lm1, 2));
        const float nm0 = fmaxf(m0, lm0), nm1 = fmaxf(m1, lm1);
        const float c0 = __expf(m0 - nm0), c1 = __expf(m1 - nm1);
        m0 = nm0; m1 = nm1;

        float ps0 = 0.f, ps1 = 0.f;
#pragma unroll
        for (int nb = 0; nb < 8; nb++) {
            s[nb][0] = __expf(s[nb][0] - m0);
            s[nb][1] = __expf(s[nb][1] - m0);
            s[nb][2] = __expf(s[nb][2] - m1);
            s[nb][3] = __expf(s[nb][3] - m1);
            ps0 += s[nb][0] + s[nb][1];
            ps1 += s[nb][2] + s[nb][3];
        }
        ps0 += __shfl_xor_sync(0xffffffffu, ps0, 1);
        ps0 += __shfl_xor_sync(0xffffffffu, ps0, 2);
        ps1 += __shfl_xor_sync(0xffffffffu, ps1, 1);
        ps1 += __shfl_xor_sync(0xffffffffu, ps1, 2);
        l0 = l0 * c0 + ps0;
        l1 = l1 * c1 + ps1;
#pragma unroll
        for (int nd = 0; nd < 8; nd++) {
            o[nd][0] *= c0; o[nd][1] *= c0;
            o[nd][2] *= c1; o[nd][3] *= c1;
        }

        // P -> fp16 register fragments
        uint32_t p01[8], p23[8];
#pragma unroll
        for (int nb = 0; nb < 8; nb++) {
            p01[nb] = h2u(__floats2half2_rn(s[nb][0], s[nb][1]));
            p23[nb] = h2u(__floats2half2_rn(s[nb][2], s[nb][3]));
        }

        // O += P V (B from transposed V tile)
#pragma unroll
        for (int c = 0; c < 4; c++) {
            const uint32_t a0 = p01[2 * c], a1 = p23[2 * c];
            const uint32_t a2 = p01[2 * c + 1], a3 = p23[2 * c + 1];
#pragma unroll
            for (int nd = 0; nd < 8; nd++) {
                const uint32_t* vr = sVt + (nd * 8 + gr) * AST + 8 * c + tg;
                mma16h(o[nd], a0, a1, a2, a3, vr[0], vr[4]);
            }
        }
    }

    // epilogue: normalize + half store
    const float il0 = 1.f / l0, il1 = 1.f / l1;
    const int grow0 = b * SS + qbase + w * 16 + gr;
    __half* d0 = outh + (size_t)grow0 * DD + h * DK;
    __half* d1 = d0 + 8 * DD;
#pragma unroll
    for (int nd = 0; nd < 8; nd++) {
        *(__half2*)(d0 + nd * 8 + 2 * tg) = __floats2half2_rn(o[nd][0] * il0, o[nd][1] * il0);
        *(__half2*)(d1 + nd * 8 + 2 * tg) = __floats2half2_rn(o[nd][2] * il1, o[nd][3] * il1);
    }
}

// ---------------- LayerNorm with fused residual add ------------------------
// in = half GEMM output (pre-residual), resid = fp32 residual stream.
// x = resid + in; LN(x) -> out (fp32) and outh (half). Warp-per-row, coalesced.
__global__ __launch_bounds__(256)
void ln_res_kernel(const __half* __restrict__ inh, const float* __restrict__ resid,
                   const float* __restrict__ gamma, const float* __restrict__ beta,
                   float* __restrict__ out, __half* __restrict__ outh)
{
    const int wid = threadIdx.x >> 5;
    const int lane = threadIdx.x & 31;
    const int row = blockIdx.x * 8 + wid;
    const float4* rr = (const float4*)(resid + (size_t)row * DD);
    const uint2* ih = (const uint2*)(inh + (size_t)row * DD);   // 4 halves per uint2

    float4 v[4];
#pragma unroll
    for (int i = 0; i < 4; i++) {
        const int idx = lane + 32 * i;
        float4 rv = rr[idx];
        uint2 hu = ih[idx];
        __half2 h0 = *(__half2*)&hu.x;
        __half2 h1 = *(__half2*)&hu.y;
        float2 f0 = __half22float2(h0);
        float2 f1 = __half22float2(h1);
        v[i].x = rv.x + f0.x;
        v[i].y = rv.y + f0.y;
        v[i].z = rv.z + f1.x;
        v[i].w = rv.w + f1.y;
    }

    float s = 0.f, sq = 0.f;
#pragma unroll
    for (int i = 0; i < 4; i++) {
        s  += v[i].x + v[i].y + v[i].z + v[i].w;
        sq += v[i].x * v[i].x + v[i].y * v[i].y + v[i].z * v[i].z + v[i].w * v[i].w;
    }
#pragma unroll
    for (int off = 16; off > 0; off >>= 1) {
        s  += __shfl_xor_sync(0xffffffffu, s,  off);
        sq += __shfl_xor_sync(0xffffffffu, sq, off);
    }

    const float mean = s * (1.f / DD);
    const float var  = sq * (1.f / DD) - mean * mean;
    const float rstd = rsqrtf(var + EPS);

    const float4* gp = (const float4*)gamma;
    const float4* bp = (const float4*)beta;
    float4* op = (float4*)(out + (size_t)row * DD);
    __half2* hp = (__half2*)(outh + (size_t)row * DD);

#pragma unroll
    for (int i = 0; i < 4; i++) {
        const int idx = lane + 32 * i;
        const float4 gv = gp[idx];
        const float4 bv = bp[idx];
        float4 r;
        r.x = (v[i].x - mean) * rstd * gv.x + bv.x;
        r.y = (v[i].y - mean) * rstd * gv.y + bv.y;
        r.z = (v[i].z - mean) * rstd * gv.z + bv.z;
        r.w = (v[i].w - mean) * rstd * gv.w + bv.w;
        op[idx] = r;
        hp[2 * idx]     = __floats2half2_rn(r.x, r.y);
        hp[2 * idx + 1] = __floats2half2_rn(r.z, r.w);
    }
}

// ---------------- driver ----------------
extern "C" void kernel_launch(void* const* d_in, const int* in_sizes, int n_in,
                              void* d_out, int out_size)
{
    const float* x      = (const float*)d_in[0];
    const float* qkv_w  = (const float*)d_in[1];
    const float* qkv_b  = (const float*)d_in[2];
    const float* out_w  = (const float*)d_in[3];
    const float* out_b  = (const float*)d_in[4];
    const float* ln1_g  = (const float*)d_in[5];
    const float* ln1_b  = (const float*)d_in[6];
    const float* mlp_w1 = (const float*)d_in[7];
    const float* mlp_b1 = (const float*)d_in[8];
    const float* mlp_w2 = (const float*)d_in[9];
    const float* mlp_b2 = (const float*)d_in[10];
    const float* ln2_g  = (const float*)d_in[11];
    const float* ln2_b  = (const float*)d_in[12];
    float* outp = (float*)d_out;

    float *px;
    __half *pxh, *pqkvh, *pattnh, *phh, *pt2h, *pqkvwt, *poutwt, *pw1t, *pw2t;
    cudaGetSymbolAddress((void**)&px,    g_x);
    cudaGetSymbolAddress((void**)&pxh,   g_xh);
    cudaGetSymbolAddress((void**)&pqkvh, g_qkvh);
    cudaGetSymbolAddress((void**)&pattnh,g_attnh);
    cudaGetSymbolAddress((void**)&phh,   g_hh);
    cudaGetSymbolAddress((void**)&pt2h,  g_t2h);
    cudaGetSymbolAddress((void**)&pqkvwt,g_qkv_wt);
    cudaGetSymbolAddress((void**)&poutwt,g_out_wt);
    cudaGetSymbolAddress((void**)&pw1t,  g_w1t);
    cudaGetSymbolAddress((void**)&pw2t,  g_w2t);

    cudaFuncSetAttribute(tc_gemm<false,true>, cudaFuncAttributeMaxDynamicSharedMemorySize, GSMEM_BYTES);
    cudaFuncSetAttribute(tc_gemm<true,true>,  cudaFuncAttributeMaxDynamicSharedMemorySize, GSMEM_BYTES);

    transpose_h<<<dim3(3*DD/32, DD/32, LL), dim3(32,8)>>>(qkv_w, pqkvwt, DD, 3*DD);
    transpose_h<<<dim3(DD/32,   DD/32, LL), dim3(32,8)>>>(out_w, poutwt, DD, DD);
    transpose_h<<<dim3(DFF/32,  DD/32, LL), dim3(32,8)>>>(mlp_w1, pw1t, DD, DFF);
    transpose_h<<<dim3(DD/32,  DFF/32, LL), dim3(32,8)>>>(mlp_w2, pw2t, DFF, DD);

    const int nX = MM * DD;
    copy_half_kernel<<<(nX/4 + 255)/256, 256>>>((const float4*)x, (float4*)px,
                                                (__half2*)pxh, nX/4);

    for (int i = 0; i < LL; i++) {
        // QKV: [8192,512] x [512,1536] (+bias) -> half
        tc_gemm<false,true><<<dim3(3*DD/BN, MM/BM), 256, GSMEM_BYTES>>>(
            pxh, pqkvwt + (size_t)i * 3*DD*DD, qkv_b + (size_t)i * 3*DD,
            pqkvh, MM, 3*DD, DD);

        attn_h_kernel<<<dim3(SS/128, HH, BB), 256>>>(pqkvh, pattnh);

        // out-proj (raw, no residual) -> half t2h
        tc_gemm<false,true><<<dim3(DD/BN, MM/BM), 256, GSMEM_BYTES>>>(
            pattnh, poutwt + (size_t)i * DD*DD, out_b + (size_t)i * DD,
            pt2h, MM, DD, DD);

        // LN1(resid + t2h) -> px (fp32) + pxh (half)
        ln_res_kernel<<<MM/8, 256>>>(pt2h, px, ln1_g + (size_t)i * DD,
                                     ln1_b + (size_t)i * DD, px, pxh);

        // MLP1 + ReLU -> half hh
        tc_gemm<true,true><<<dim3(DFF/BN, MM/BM), 256, GSMEM_BYTES>>>(
            pxh, pw1t + (size_t)i * DFF*DD, mlp_b1 + (size_t)i * DFF,
            phh, MM, DFF, DD);

        // MLP2 (raw, no residual) -> half t2h
        tc_gemm<false,true><<<dim3(DD/BN, MM/BM), 256, GSMEM_BYTES>>>(
            phh, pw2t + (size_t)i * DD*DFF, mlp_b2 + (size_t)i * DD,
            pt2h, MM, DD, DFF);

        // LN2(resid + t2h) -> next x
        float* lnout = (i == LL - 1) ? outp : px;
        ln_res_kernel<<<MM/8, 256>>>(pt2h, px, ln2_g + (size_t)i * DD,
                                     ln2_b + (size_t)i * DD, lnout, pxh);
    }
}